// round 13
// baseline (speedup 1.0000x reference)
#include <cuda_runtime.h>
#include <math.h>
#include <stdint.h>

#define N_NODES  20000
#define N_EDGES  128000
#define N_GRAPHS 64
#define FEAT     100
#define HID      256
#define HEADS    4
#define HC       1024
#define N_ETYPES 100

#define MP   20096     // N_NODES padded to multiple of 128 (157*128)
#define KP1  112       // FEAT padded to multiple of 16

// ---------------- scratch (static device globals; no runtime alloc) --------
__device__ float g_xT[KP1 * MP];            // layer-1 input, TRANSPOSED [K][M]
__device__ float g_W1p[KP1 * HC];           // W1 zero-padded to 112 rows
__device__ float g_h[MP * HC];              // h1 = X @ W1
__device__ float g_feat[MP * HC];           // F2 = ELU(agg1 + b1)
__device__ float g_als[N_NODES * HEADS];
__device__ float g_ald[N_NODES * HEADS];
__device__ float g_u[2 * HC * HEADS];       // We folds, both layers
__device__ float g_alet[2 * N_ETYPES * HEADS];
__device__ float g_alpha[N_EDGES * HEADS];
__device__ int   g_cnt[N_NODES];
__device__ int   g_cur[N_NODES];
__device__ int   g_off[N_NODES + 1];
__device__ int   g_perm[N_EDGES];
__device__ float g_gcnt[N_GRAPHS];
// algebraic-path buffers
__device__ float g_v[HC * 8];               // W2 folded with a_src2/a_dst2
__device__ float g_v1[FEAT * 8];            // W1 folded with a_src1/a_dst1
__device__ float g_W2T[HC * HC];            // W2 transposed
__device__ float g_Q[HEADS * HC * HID];     // Q_h = W2[:,hchunk] @ projW[hchunk,:]
__device__ float g_E[N_GRAPHS * HEADS * HC];// edge-weighted F2 sums per (g,h)
__device__ float g_cvec[HID];               // b2@projW + projb

// ================= pipelined fp32 SGEMM (R6 core — proven best) ============
#define CPA16U(dst_u32, src_ptr) \
    asm volatile("cp.async.cg.shared.global [%0], [%1], 16;\n" \
                 :: "r"(dst_u32), "l"(src_ptr))
#define CPA_COMMIT() asm volatile("cp.async.commit_group;\n" ::: "memory")

__global__ __launch_bounds__(256) void k_sgemm(const float* __restrict__ AT,
                                               const float* __restrict__ B,
                                               float* __restrict__ C,
                                               int K) {
    __shared__ __align__(16) float As[2][16][128];
    __shared__ __align__(16) float Bs[2][16][128];
    const int tid = threadIdx.x;
    const int bm = blockIdx.y * 128, bn = blockIdx.x * 128;
    const int warp = tid >> 5, lane = tid & 31;
    const int wm = warp & 3, wn = warp >> 2;
    const int ly = lane >> 3, lx = lane & 7;
    const int arow = wm * 32 + ly * 8;
    const int bcol = wn * 64 + lx * 8;

    float acc[8][8];
    #pragma unroll
    for (int m = 0; m < 8; m++)
        #pragma unroll
        for (int n = 0; n < 8; n++) acc[m][n] = 0.f;

    const int S = K >> 4;

    auto load_tiles = [&](int s, int t) {
        const int k0 = t << 4;
        #pragma unroll
        for (int j = 0; j < 2; j++) {
            int id = tid + j * 256;
            int r = id >> 5;
            int c4 = (id & 31) * 4;
            uint32_t sa = (uint32_t)__cvta_generic_to_shared(&As[s][r][c4]);
            CPA16U(sa, AT + (long)(k0 + r) * MP + bm + c4);
            uint32_t sb = (uint32_t)__cvta_generic_to_shared(&Bs[s][r][c4]);
            CPA16U(sb, B + (long)(k0 + r) * HC + bn + c4);
        }
    };

    load_tiles(0, 0);
    CPA_COMMIT();

    for (int t = 0; t < S; t++) {
        const int cur = t & 1;
        if (t + 1 < S) {
            load_tiles((t + 1) & 1, t + 1);
            CPA_COMMIT();
            asm volatile("cp.async.wait_group 1;\n" ::: "memory");
        } else {
            asm volatile("cp.async.wait_group 0;\n" ::: "memory");
        }
        __syncthreads();

        #pragma unroll
        for (int k = 0; k < 16; k++) {
            float4 a0 = *(const float4*)&As[cur][k][arow];
            float4 a1 = *(const float4*)&As[cur][k][arow + 4];
            float4 b0 = *(const float4*)&Bs[cur][k][bcol];
            float4 b1 = *(const float4*)&Bs[cur][k][bcol + 4];
            float ra[8] = {a0.x, a0.y, a0.z, a0.w, a1.x, a1.y, a1.z, a1.w};
            float rb[8] = {b0.x, b0.y, b0.z, b0.w, b1.x, b1.y, b1.z, b1.w};
            #pragma unroll
            for (int m = 0; m < 8; m++)
                #pragma unroll
                for (int n = 0; n < 8; n++) acc[m][n] += ra[m] * rb[n];
        }
        __syncthreads();
    }

    #pragma unroll
    for (int mi = 0; mi < 8; mi++) {
        float* cp = C + (long)(bm + arow + mi) * HC + bn + bcol;
        *(float4*)cp = make_float4(acc[mi][0], acc[mi][1], acc[mi][2], acc[mi][3]);
        *(float4*)(cp + 4) = make_float4(acc[mi][4], acc[mi][5], acc[mi][6], acc[mi][7]);
    }
}

// ---- small GEMM for Q_h: C_h[1024x256] = W2T_h^T @ projW_h ----------------
__global__ __launch_bounds__(256) void k_qfold(const float* __restrict__ W2T,
                                               const float* __restrict__ projW) {
    const float* AT = W2T + (long)blockIdx.z * 256 * HC;
    const float* B  = projW + (long)blockIdx.z * 256 * HID;
    float* C = g_Q + (long)blockIdx.z * HC * HID;
    __shared__ __align__(16) float As[2][16][128];
    __shared__ __align__(16) float Bs[2][16][128];
    const int tid = threadIdx.x;
    const int bm = blockIdx.y * 128, bn = blockIdx.x * 128;
    const int warp = tid >> 5, lane = tid & 31;
    const int wm = warp & 3, wn = warp >> 2;
    const int ly = lane >> 3, lx = lane & 7;
    const int arow = wm * 32 + ly * 8;
    const int bcol = wn * 64 + lx * 8;

    float acc[8][8];
    #pragma unroll
    for (int m = 0; m < 8; m++)
        #pragma unroll
        for (int n = 0; n < 8; n++) acc[m][n] = 0.f;

    const int S = 256 >> 4;

    auto load_tiles = [&](int s, int t) {
        const int k0 = t << 4;
        #pragma unroll
        for (int j = 0; j < 2; j++) {
            int id = tid + j * 256;
            int r = id >> 5;
            int c4 = (id & 31) * 4;
            uint32_t sa = (uint32_t)__cvta_generic_to_shared(&As[s][r][c4]);
            CPA16U(sa, AT + (long)(k0 + r) * HC + bm + c4);
            uint32_t sb = (uint32_t)__cvta_generic_to_shared(&Bs[s][r][c4]);
            CPA16U(sb, B + (long)(k0 + r) * HID + bn + c4);
        }
    };

    load_tiles(0, 0);
    CPA_COMMIT();

    for (int t = 0; t < S; t++) {
        const int cur = t & 1;
        if (t + 1 < S) {
            load_tiles((t + 1) & 1, t + 1);
            CPA_COMMIT();
            asm volatile("cp.async.wait_group 1;\n" ::: "memory");
        } else {
            asm volatile("cp.async.wait_group 0;\n" ::: "memory");
        }
        __syncthreads();
        #pragma unroll
        for (int k = 0; k < 16; k++) {
            float4 a0 = *(const float4*)&As[cur][k][arow];
            float4 a1 = *(const float4*)&As[cur][k][arow + 4];
            float4 b0 = *(const float4*)&Bs[cur][k][bcol];
            float4 b1 = *(const float4*)&Bs[cur][k][bcol + 4];
            float ra[8] = {a0.x, a0.y, a0.z, a0.w, a1.x, a1.y, a1.z, a1.w};
            float rb[8] = {b0.x, b0.y, b0.z, b0.w, b1.x, b1.y, b1.z, b1.w};
            #pragma unroll
            for (int m = 0; m < 8; m++)
                #pragma unroll
                for (int n = 0; n < 8; n++) acc[m][n] += ra[m] * rb[n];
        }
        __syncthreads();
    }

    #pragma unroll
    for (int mi = 0; mi < 8; mi++) {
        float* cp = C + (long)(bm + arow + mi) * HID + bn + bcol;
        *(float4*)cp = make_float4(acc[mi][0], acc[mi][1], acc[mi][2], acc[mi][3]);
        *(float4*)(cp + 4) = make_float4(acc[mi][4], acc[mi][5], acc[mi][6], acc[mi][7]);
    }
}

// ---------------- input prep ------------------------------------------------
__global__ void k_gatherT(const int* __restrict__ x_idx,
                          const float* __restrict__ node_emb) {
    int n = blockIdx.x * 256 + threadIdx.x;
    int f = blockIdx.y;
    if (n < MP) {
        float v = 0.f;
        if (n < N_NODES && f < FEAT) v = node_emb[(long)x_idx[n] * FEAT + f];
        g_xT[(long)f * MP + n] = v;
    }
}

__global__ void k_prep1(const float* __restrict__ W1) {
    int i = blockIdx.x * 256 + threadIdx.x;
    if (i < KP1 * HC) {
        int r = i >> 10;
        g_W1p[i] = (r < FEAT) ? W1[i] : 0.f;
    }
    if (i < N_NODES) { g_cnt[i] = 0; g_cur[i] = 0; }
    if (i < N_GRAPHS * HEADS * HC) g_E[i] = 0.f;
    if (i < N_GRAPHS) g_gcnt[i] = 0.f;
}

__global__ __launch_bounds__(256) void k_w2t(const float* __restrict__ W2) {
    __shared__ float tile[32][33];
    int m0 = blockIdx.x * 32, k0 = blockIdx.y * 32;
    int tx = threadIdx.x, ty = threadIdx.y;
    #pragma unroll
    for (int i = ty; i < 32; i += 8)
        tile[i][tx] = W2[(long)(m0 + i) * HC + k0 + tx];
    __syncthreads();
    #pragma unroll
    for (int i = ty; i < 32; i += 8)
        g_W2T[(long)(k0 + i) * HC + m0 + tx] = tile[tx][i];
}

// ---------------- CSR build ------------------------------------------------
__global__ void k_csr_count(const int* __restrict__ dst) {
    int e = blockIdx.x * blockDim.x + threadIdx.x;
    if (e < N_EDGES) atomicAdd(&g_cnt[dst[e]], 1);
}
__global__ void k_csr_scan() {
    __shared__ int s[1024];
    int tid = threadIdx.x;
    int carry = 0;
    for (int base = 0; base < N_NODES; base += 1024) {
        int i = base + tid;
        int v = (i < N_NODES) ? g_cnt[i] : 0;
        s[tid] = v;
        __syncthreads();
        #pragma unroll
        for (int off = 1; off < 1024; off <<= 1) {
            int t = (tid >= off) ? s[tid - off] : 0;
            __syncthreads();
            s[tid] += t;
            __syncthreads();
        }
        if (i < N_NODES) g_off[i] = carry + s[tid] - v;
        carry += s[1023];
        __syncthreads();
    }
    if (tid == 0) g_off[N_NODES] = carry;
}
__global__ void k_csr_scatter(const int* __restrict__ dst) {
    int e = blockIdx.x * blockDim.x + threadIdx.x;
    if (e < N_EDGES) {
        int d = dst[e];
        int p = atomicAdd(&g_cur[d], 1);
        g_perm[g_off[d] + p] = e;
    }
}

// ---------------- generic fold W·a (src/dst) -> out[k*8+j] -----------------
__global__ void k_fold_v(const float* __restrict__ W,
                         const float* __restrict__ a_s,
                         const float* __restrict__ a_d,
                         float* __restrict__ out, int K) {
    int wid = (blockIdx.x * blockDim.x + threadIdx.x) >> 5;
    int lane = threadIdx.x & 31;
    if (wid >= K * 8) return;
    int k = wid >> 3, j = wid & 7;
    const float* a = (j < 4) ? (a_s + j * HID) : (a_d + (j - 4) * HID);
    int cb = (j & 3) * HID;
    float s = 0.f;
    #pragma unroll
    for (int c = lane; c < HID; c += 32)
        s += W[(long)k * HC + cb + c] * a[c];
    #pragma unroll
    for (int o = 16; o; o >>= 1) s += __shfl_down_sync(0xffffffffu, s, o);
    if (lane == 0) out[k * 8 + j] = s;
}

// layer-1 attention scalars from X directly: als1 = X @ v1
__global__ void k_al1() {
    int n = blockIdx.x * 256 + threadIdx.x;
    if (n >= N_NODES) return;
    float p[8];
    #pragma unroll
    for (int j = 0; j < 8; j++) p[j] = 0.f;
    for (int k = 0; k < FEAT; k++) {
        float x = g_xT[(long)k * MP + n];
        #pragma unroll
        for (int j = 0; j < 8; j++) p[j] += x * g_v1[k * 8 + j];
    }
    #pragma unroll
    for (int j = 0; j < 4; j++) {
        g_als[n * HEADS + j] = p[j];
        g_ald[n * HEADS + j] = p[j + 4];
    }
}

// ---------------- edge-type terms: both layers in one kernel each ----------
__global__ void k_fold_u2(const float* __restrict__ We1,
                          const float* __restrict__ a_edge1,
                          const float* __restrict__ We2,
                          const float* __restrict__ a_edge2) {
    int wid = (blockIdx.x * blockDim.x + threadIdx.x) >> 5;
    int lane = threadIdx.x & 31;
    if (wid >= 2 * HC * HEADS) return;
    int layer = wid >= HC * HEADS;
    int w = wid - layer * HC * HEADS;
    int k = w >> 2, hh = w & 3;
    const float* We = layer ? We2 : We1;
    const float* ae = layer ? a_edge2 : a_edge1;
    float s = 0.f;
    #pragma unroll
    for (int c = lane; c < HID; c += 32)
        s += We[(long)k * HC + hh * HID + c] * ae[hh * HID + c];
    #pragma unroll
    for (int o = 16; o; o >>= 1) s += __shfl_down_sync(0xffffffffu, s, o);
    if (lane == 0) g_u[layer * HC * HEADS + k * HEADS + hh] = s;
}

__global__ void k_alet2(const float* __restrict__ edge_emb) {
    int wid = (blockIdx.x * blockDim.x + threadIdx.x) >> 5;
    int lane = threadIdx.x & 31;
    if (wid >= 2 * N_ETYPES * HEADS) return;
    int layer = wid >= N_ETYPES * HEADS;
    int w = wid - layer * N_ETYPES * HEADS;
    int t = w >> 2, hh = w & 3;
    const float* u = g_u + layer * HC * HEADS;
    float s = 0.f;
    for (int k = lane; k < HC; k += 32)
        s += edge_emb[(long)t * HC + k] * u[k * HEADS + hh];
    #pragma unroll
    for (int o = 16; o; o >>= 1) s += __shfl_down_sync(0xffffffffu, s, o);
    if (lane == 0) g_alet[layer * N_ETYPES * HEADS + t * HEADS + hh] = s;
}

// ---------------- fused logits + segment softmax ---------------------------
__global__ void k_softmax(const int* __restrict__ src,
                          const int* __restrict__ etype, int layer) {
    int idx = blockIdx.x * blockDim.x + threadIdx.x;
    if (idx >= N_NODES * HEADS) return;
    int n = idx >> 2, hh = idx & 3;
    int a = g_off[n], b = g_off[n + 1];
    const float* alet = g_alet + layer * N_ETYPES * HEADS;
    float ald_n = g_ald[n * HEADS + hh];          // dst == n for all edges here
    float m = -1e30f;
    for (int j = a; j < b; j++) {
        int e = g_perm[j];
        float l = g_als[src[e] * HEADS + hh] + ald_n + alet[etype[e] * HEADS + hh];
        l = (l >= 0.f) ? l : 0.2f * l;            // leaky relu
        g_alpha[e * HEADS + hh] = l;
        m = fmaxf(m, l);
    }
    float den = 0.f;
    for (int j = a; j < b; j++) {
        int e = g_perm[j];
        float v = expf(g_alpha[e * HEADS + hh] - m);
        den += v;
        g_alpha[e * HEADS + hh] = v;
    }
    float inv = 1.f / (den + 1e-16f);
    for (int j = a; j < b; j++)
        g_alpha[g_perm[j] * HEADS + hh] *= inv;
}

// ---------------- layer-1 aggregation + fused layer-2 attention scalars ----
__global__ __launch_bounds__(256) void k_aggregate(const float* __restrict__ h,
                                                   const float* __restrict__ bias,
                                                   float* __restrict__ out,
                                                   const int* __restrict__ src) {
    int n = blockIdx.x;
    int tid = threadIdx.x;
    float acc0 = 0.f, acc1 = 0.f, acc2 = 0.f, acc3 = 0.f;
    int a = g_off[n], b = g_off[n + 1];
    for (int j = a; j < b; j++) {
        int e = g_perm[j];
        const float* hp = h + (long)src[e] * HC;
        float4 al = *(const float4*)&g_alpha[e * 4];
        acc0 += al.x * hp[tid];
        acc1 += al.y * hp[tid + 256];
        acc2 += al.z * hp[tid + 512];
        acc3 += al.w * hp[tid + 768];
    }
    float v[4] = {acc0 + bias[tid], acc1 + bias[tid + 256],
                  acc2 + bias[tid + 512], acc3 + bias[tid + 768]};
    #pragma unroll
    for (int t = 0; t < 4; t++) {
        float x = v[t];
        v[t] = (x > 0.f) ? x : (expf(x) - 1.f);       // ELU
        out[(long)n * HC + tid + t * 256] = v[t];
    }

    // fused: layer-2 attention scalars als2/ald2 = F2[n] . v[:,j]
    float p[8];
    #pragma unroll
    for (int j = 0; j < 8; j++) p[j] = 0.f;
    #pragma unroll
    for (int t = 0; t < 4; t++) {
        const float* vp = &g_v[(tid + t * 256) * 8];
        #pragma unroll
        for (int j = 0; j < 8; j++) p[j] += v[t] * vp[j];
    }
    int lane = tid & 31, w = tid >> 5;
    #pragma unroll
    for (int j = 0; j < 8; j++) {
        #pragma unroll
        for (int o = 16; o; o >>= 1)
            p[j] += __shfl_down_sync(0xffffffffu, p[j], o);
    }
    __shared__ float ws[8][8];
    if (lane == 0) {
        #pragma unroll
        for (int j = 0; j < 8; j++) ws[w][j] = p[j];
    }
    __syncthreads();
    if (tid < 8) {
        float s = 0.f;
        #pragma unroll
        for (int w2 = 0; w2 < 8; w2++) s += ws[w2][tid];
        if (tid < 4) g_als[n * HEADS + tid] = s;
        else         g_ald[n * HEADS + (tid - 4)] = s;
    }
}

// ---------------- layer-2: edge-parallel weighted F2 sums ------------------
__global__ __launch_bounds__(256) void k_eagg2(const float* __restrict__ F2,
                                               const int* __restrict__ src,
                                               const int* __restrict__ dst,
                                               const int* __restrict__ batch) {
    __shared__ int   s_src[256];
    __shared__ int   s_g[256];
    __shared__ float4 s_al[256];
    int tid = threadIdx.x;
    int j0 = blockIdx.x * 256;
    {
        int e = g_perm[j0 + tid];
        s_src[tid] = src[e];
        s_g[tid] = batch[dst[e]];
        s_al[tid] = *(const float4*)&g_alpha[e * 4];
    }
    __syncthreads();

    const int c = tid * 4;
    float a0[4] = {0.f, 0.f, 0.f, 0.f};
    float a1[4] = {0.f, 0.f, 0.f, 0.f};
    float a2[4] = {0.f, 0.f, 0.f, 0.f};
    float a3[4] = {0.f, 0.f, 0.f, 0.f};
    int curg = s_g[0];

    auto flush = [&](int g) {
        #pragma unroll
        for (int q = 0; q < 4; q++) {
            if (a0[q] != 0.f) atomicAdd(&g_E[(g * HEADS + 0) * HC + c + q], a0[q]);
            if (a1[q] != 0.f) atomicAdd(&g_E[(g * HEADS + 1) * HC + c + q], a1[q]);
            if (a2[q] != 0.f) atomicAdd(&g_E[(g * HEADS + 2) * HC + c + q], a2[q]);
            if (a3[q] != 0.f) atomicAdd(&g_E[(g * HEADS + 3) * HC + c + q], a3[q]);
            a0[q] = a1[q] = a2[q] = a3[q] = 0.f;
        }
    };

    for (int i = 0; i < 256; i++) {
        int g = s_g[i];
        if (g != curg) { flush(curg); curg = g; }
        float4 f = *(const float4*)(F2 + (long)s_src[i] * HC + c);
        float4 al = s_al[i];
        a0[0] += al.x * f.x; a0[1] += al.x * f.y; a0[2] += al.x * f.z; a0[3] += al.x * f.w;
        a1[0] += al.y * f.x; a1[1] += al.y * f.y; a1[2] += al.y * f.z; a1[3] += al.y * f.w;
        a2[0] += al.z * f.x; a2[1] += al.z * f.y; a2[2] += al.z * f.z; a2[3] += al.z * f.w;
        a3[0] += al.w * f.x; a3[1] += al.w * f.y; a3[2] += al.w * f.z; a3[3] += al.w * f.w;
    }
    flush(curg);
}

// ---------------- per-graph counts -----------------------------------------
__global__ void k_gcnt(const int* __restrict__ batch) {
    int i = blockIdx.x * blockDim.x + threadIdx.x;
    if (i < N_NODES) atomicAdd(&g_gcnt[batch[i]], 1.f);
}

__global__ void k_cvec(const float* __restrict__ b2,
                       const float* __restrict__ projW,
                       const float* __restrict__ projb) {
    int d = threadIdx.x;
    float s = projb[d];
    for (int k = 0; k < HC; k++) s += b2[k] * projW[(long)k * HID + d];
    g_cvec[d] = s;
}

// ---------------- final: y[g] = sum_h (E/cnt)@Q_h + cvec, LN, ReLU ---------
__global__ __launch_bounds__(256) void k_final2(const float* __restrict__ lng,
                                                const float* __restrict__ lnb,
                                                float* __restrict__ out) {
    int g = blockIdx.x;
    int d = threadIdx.x;
    __shared__ float red[256];
    float inv = 1.f / fmaxf(g_gcnt[g], 1.f);
    float acc = 0.f;
    #pragma unroll
    for (int h = 0; h < HEADS; h++) {
        const float* ep = g_E + (long)(g * HEADS + h) * HC;
        const float* qp = g_Q + (long)h * HC * HID;
        #pragma unroll 8
        for (int k = 0; k < HC; k++)
            acc += ep[k] * qp[(long)k * HID + d];
    }
    float y = acc * inv + g_cvec[d];
    red[d] = y;
    __syncthreads();
    #pragma unroll
    for (int off = 128; off; off >>= 1) {
        if (d < off) red[d] += red[d + off];
        __syncthreads();
    }
    float mu = red[0] / (float)HID;
    __syncthreads();
    float dv = y - mu;
    red[d] = dv * dv;
    __syncthreads();
    #pragma unroll
    for (int off = 128; off; off >>= 1) {
        if (d < off) red[d] += red[d + off];
        __syncthreads();
    }
    float var = red[0] / (float)HID;
    float r = dv * rsqrtf(var + 1e-5f) * lng[d] + lnb[d];
    out[g * HID + d] = fmaxf(r, 0.f);
}

// ---------------- host orchestration ---------------------------------------
static float* sym(const void* s) {
    void* p = 0;
    cudaGetSymbolAddress(&p, s);
    return (float*)p;
}

extern "C" void kernel_launch(void* const* d_in, const int* in_sizes, int n_in,
                              void* d_out, int out_size) {
    const int*   x_idx    = (const int*)d_in[0];
    const int*   eidx     = (const int*)d_in[1];
    const int*   etype    = (const int*)d_in[2];
    const int*   batch    = (const int*)d_in[3];
    const float* node_emb = (const float*)d_in[4];
    const float* edge_emb = (const float*)d_in[5];
    const float* W1     = (const float*)d_in[6];
    const float* a_src1 = (const float*)d_in[7];
    const float* a_dst1 = (const float*)d_in[8];
    const float* a_edge1= (const float*)d_in[9];
    const float* We1    = (const float*)d_in[10];
    const float* b1     = (const float*)d_in[11];
    const float* W2     = (const float*)d_in[12];
    const float* a_src2 = (const float*)d_in[13];
    const float* a_dst2 = (const float*)d_in[14];
    const float* a_edge2= (const float*)d_in[15];
    const float* We2    = (const float*)d_in[16];
    const float* b2     = (const float*)d_in[17];
    const float* projW  = (const float*)d_in[18];
    const float* projb  = (const float*)d_in[19];
    const float* lng    = (const float*)d_in[20];
    const float* lnb    = (const float*)d_in[21];
    float* out = (float*)d_out;

    const int* src = eidx;
    const int* dst = eidx + N_EDGES;

    float* p_xT   = sym(g_xT);
    float* p_W1p  = sym(g_W1p);
    float* p_W2T  = sym(g_W2T);
    float* p_h    = sym(g_h);
    float* p_feat = sym(g_feat);
    float* p_v    = sym(g_v);
    float* p_v1   = sym(g_v1);

    dim3 ggrid(HC / 128, MP / 128);            // (8, 157)
    dim3 gagrid((MP + 255) / 256, KP1);        // gatherT
    dim3 w2tgrid(HC / 32, HC / 32);            // W2 transpose
    dim3 qgrid(HID / 128, HC / 128, HEADS);    // (2, 8, 4)

    // launch order keeps the layer-1 GEMM in ncu's capture slot (#4)
    k_gatherT<<<gagrid, 256>>>(x_idx, node_emb);                    // 1
    k_prep1<<<(N_GRAPHS * HEADS * HC + 255) / 256, 256>>>(W1);      // 2
    k_csr_count<<<(N_EDGES + 255) / 256, 256>>>(dst);               // 3
    k_sgemm<<<ggrid, 256>>>(p_xT, p_W1p, p_h, KP1);                 // 4 <- ncu
    k_csr_scan<<<1, 1024>>>();                                      // 5
    k_csr_scatter<<<(N_EDGES + 255) / 256, 256>>>(dst);             // 6
    // independent prep
    k_w2t<<<w2tgrid, dim3(32, 8)>>>(W2);
    k_qfold<<<qgrid, 256>>>(p_W2T, projW);
    k_fold_v<<<(HC * 8 * 32 + 255) / 256, 256>>>(W2, a_src2, a_dst2, p_v, HC);
    k_fold_v<<<(FEAT * 8 * 32 + 255) / 256, 256>>>(W1, a_src1, a_dst1, p_v1, FEAT);
    k_cvec<<<1, HID>>>(b2, projW, projb);
    k_gcnt<<<(N_NODES + 255) / 256, 256>>>(batch);
    k_fold_u2<<<(2 * HC * HEADS * 32 + 255) / 256, 256>>>(We1, a_edge1, We2, a_edge2);
    k_alet2<<<(2 * N_ETYPES * HEADS * 32 + 255) / 256, 256>>>(edge_emb);
    k_al1<<<(N_NODES + 255) / 256, 256>>>();

    // layer 1 attention + aggregation (aggregate emits layer-2 als/ald)
    k_softmax<<<(N_NODES * HEADS + 255) / 256, 256>>>(src, etype, 0);
    k_aggregate<<<N_NODES, 256>>>(p_h, b1, p_feat, src);

    // layer 2 (algebraic path)
    k_softmax<<<(N_NODES * HEADS + 255) / 256, 256>>>(src, etype, 1);
    k_eagg2<<<N_EDGES / 256, 256>>>(p_feat, src, dst, batch);

    // head
    k_final2<<<N_GRAPHS, 256>>>(lng, lnb, out);
}

// round 14
// speedup vs baseline: 1.4792x; 1.4792x over previous
#include <cuda_runtime.h>
#include <math.h>
#include <stdint.h>

#define N_NODES  20000
#define N_EDGES  128000
#define N_GRAPHS 64
#define FEAT     100
#define HID      256
#define HEADS    4
#define HC       1024
#define N_ETYPES 100

#define MP   20096     // N_NODES padded to multiple of 128
#define KP1  112       // FEAT padded to multiple of 16
#define AXW  (HEADS * KP1)   // aggX row width = 448

// ---------------- scratch (static device globals; no runtime alloc) --------
__device__ float g_x[N_NODES * KP1];        // node features, node-major, f-padded
__device__ float g_W1p[KP1 * HC];           // W1 zero-padded to 112 rows
__device__ float g_aggX[MP * AXW];          // per-head aggregated X (pad rows stay 0)
__device__ float g_feat[MP * HC];           // F2 = ELU(aggX@W1 + b1)
__device__ float g_als[N_NODES * HEADS];
__device__ float g_ald[N_NODES * HEADS];
__device__ float g_u[2 * HC * HEADS];       // We folds, both layers
__device__ float g_alet[2 * N_ETYPES * HEADS];
__device__ float g_alpha[N_EDGES * HEADS];
__device__ int   g_cnt[N_NODES];
__device__ int   g_cur[N_NODES];
__device__ int   g_off[N_NODES + 1];
__device__ int   g_perm[N_EDGES];
__device__ float g_gcnt[N_GRAPHS];
// algebraic-path buffers
__device__ float g_v[HC * 8];               // W2 folded with a_src2/a_dst2
__device__ float g_v1[FEAT * 8];            // W1 folded with a_src1/a_dst1
__device__ float g_W2T[HC * HC];            // W2 transposed
__device__ float g_Q[HEADS * HC * HID];     // Q_h = W2[:,hchunk] @ projW[hchunk,:]
__device__ float g_E[N_GRAPHS * HEADS * HC];// edge-weighted F2 sums per (g,h)
__device__ float g_part[N_GRAPHS * HEADS * HID]; // head partials
__device__ float g_cvec[HID];               // b2@projW + projb

#define CPA16U(dst_u32, src_ptr) \
    asm volatile("cp.async.cg.shared.global [%0], [%1], 16;\n" \
                 :: "r"(dst_u32), "l"(src_ptr))
#define CPA_COMMIT() asm volatile("cp.async.commit_group;\n" ::: "memory")

// ============ head-blocked GEMM: F2[:,h·256+j] = aggX[:,h-slice] @ W1p[:,..]
// A row-major (smem-transposed on load), B via cp.async, bias+ELU epilogue.
__global__ __launch_bounds__(256) void k_gemmF(const float* __restrict__ aggX,
                                               const float* __restrict__ W1p,
                                               const float* __restrict__ b1,
                                               float* __restrict__ F2) {
    __shared__ __align__(16) float As[2][16][132];
    __shared__ __align__(16) float Bs[2][16][128];
    const int tid = threadIdx.x;
    const int h = blockIdx.z;
    const int bm = blockIdx.y * 128;
    const int bncol = h * 256 + blockIdx.x * 128;
    const int warp = tid >> 5, lane = tid & 31;
    const int wm = warp & 3, wn = warp >> 2;
    const int ly = lane >> 3, lx = lane & 7;
    const int arow = wm * 32 + ly * 8;
    const int bcol = wn * 64 + lx * 8;

    // this thread's two A chunks: id = tid + j*256 -> m = id>>2, kc = (id&3)*4
    const int am0 = tid >> 2, akc0 = (tid & 3) * 4;
    const int am1 = (tid + 256) >> 2, akc1 = ((tid + 256) & 3) * 4;

    float acc[8][8];
    #pragma unroll
    for (int m = 0; m < 8; m++)
        #pragma unroll
        for (int n = 0; n < 8; n++) acc[m][n] = 0.f;

    const int S = KP1 / 16;    // 7

    auto load_B = [&](int s, int t) {
        const int k0 = t << 4;
        #pragma unroll
        for (int j = 0; j < 2; j++) {
            int id = tid + j * 256;
            int r = id >> 5, c4 = (id & 31) * 4;
            uint32_t sb = (uint32_t)__cvta_generic_to_shared(&Bs[s][r][c4]);
            CPA16U(sb, W1p + (long)(k0 + r) * HC + bncol + c4);
        }
    };
    auto load_A_regs = [&](float4* ar, int t) {
        const int k0 = t << 4;
        ar[0] = *(const float4*)(aggX + (long)(bm + am0) * AXW + h * KP1 + k0 + akc0);
        ar[1] = *(const float4*)(aggX + (long)(bm + am1) * AXW + h * KP1 + k0 + akc1);
    };
    auto store_A = [&](int s, const float4* ar) {
        As[s][akc0 + 0][am0] = ar[0].x; As[s][akc0 + 1][am0] = ar[0].y;
        As[s][akc0 + 2][am0] = ar[0].z; As[s][akc0 + 3][am0] = ar[0].w;
        As[s][akc1 + 0][am1] = ar[1].x; As[s][akc1 + 1][am1] = ar[1].y;
        As[s][akc1 + 2][am1] = ar[1].z; As[s][akc1 + 3][am1] = ar[1].w;
    };

    {
        float4 ar[2];
        load_A_regs(ar, 0);
        load_B(0, 0);
        CPA_COMMIT();
        store_A(0, ar);
        asm volatile("cp.async.wait_group 0;\n" ::: "memory");
        __syncthreads();
    }

    for (int t = 0; t < S; t++) {
        const int cur = t & 1;
        float4 an[2];
        if (t + 1 < S) {
            load_B(cur ^ 1, t + 1);
            CPA_COMMIT();
            load_A_regs(an, t + 1);
        }
        #pragma unroll
        for (int k = 0; k < 16; k++) {
            float4 a0 = *(const float4*)&As[cur][k][arow];
            float4 a1 = *(const float4*)&As[cur][k][arow + 4];
            float4 b0 = *(const float4*)&Bs[cur][k][bcol];
            float4 b1v = *(const float4*)&Bs[cur][k][bcol + 4];
            float ra[8] = {a0.x, a0.y, a0.z, a0.w, a1.x, a1.y, a1.z, a1.w};
            float rb[8] = {b0.x, b0.y, b0.z, b0.w, b1v.x, b1v.y, b1v.z, b1v.w};
            #pragma unroll
            for (int m = 0; m < 8; m++)
                #pragma unroll
                for (int n = 0; n < 8; n++) acc[m][n] += ra[m] * rb[n];
        }
        if (t + 1 < S) {
            asm volatile("cp.async.wait_group 0;\n" ::: "memory");
            store_A(cur ^ 1, an);
        }
        __syncthreads();
    }

    // epilogue: + bias, ELU, store
    #pragma unroll
    for (int mi = 0; mi < 8; mi++) {
        float* cp = F2 + (long)(bm + arow + mi) * HC + bncol + bcol;
        float o[8];
        #pragma unroll
        for (int n = 0; n < 8; n++) {
            float x = acc[mi][n] + b1[bncol + bcol + n];
            o[n] = (x > 0.f) ? x : (expf(x) - 1.f);
        }
        *(float4*)cp = make_float4(o[0], o[1], o[2], o[3]);
        *(float4*)(cp + 4) = make_float4(o[4], o[5], o[6], o[7]);
    }
}

// ---- small GEMM for Q_h: C_h[1024x256] = W2T_h^T @ projW_h ----------------
__global__ __launch_bounds__(256) void k_qfold(const float* __restrict__ W2T,
                                               const float* __restrict__ projW) {
    const float* AT = W2T + (long)blockIdx.z * 256 * HC;
    const float* B  = projW + (long)blockIdx.z * 256 * HID;
    float* C = g_Q + (long)blockIdx.z * HC * HID;
    __shared__ __align__(16) float As[2][16][128];
    __shared__ __align__(16) float Bs[2][16][128];
    const int tid = threadIdx.x;
    const int bm = blockIdx.y * 128, bn = blockIdx.x * 128;
    const int warp = tid >> 5, lane = tid & 31;
    const int wm = warp & 3, wn = warp >> 2;
    const int ly = lane >> 3, lx = lane & 7;
    const int arow = wm * 32 + ly * 8;
    const int bcol = wn * 64 + lx * 8;

    float acc[8][8];
    #pragma unroll
    for (int m = 0; m < 8; m++)
        #pragma unroll
        for (int n = 0; n < 8; n++) acc[m][n] = 0.f;

    const int S = 256 >> 4;

    auto load_tiles = [&](int s, int t) {
        const int k0 = t << 4;
        #pragma unroll
        for (int j = 0; j < 2; j++) {
            int id = tid + j * 256;
            int r = id >> 5, c4 = (id & 31) * 4;
            uint32_t sa = (uint32_t)__cvta_generic_to_shared(&As[s][r][c4]);
            CPA16U(sa, AT + (long)(k0 + r) * HC + bm + c4);
            uint32_t sb = (uint32_t)__cvta_generic_to_shared(&Bs[s][r][c4]);
            CPA16U(sb, B + (long)(k0 + r) * HID + bn + c4);
        }
    };

    load_tiles(0, 0);
    CPA_COMMIT();

    for (int t = 0; t < S; t++) {
        const int cur = t & 1;
        if (t + 1 < S) {
            load_tiles((t + 1) & 1, t + 1);
            CPA_COMMIT();
            asm volatile("cp.async.wait_group 1;\n" ::: "memory");
        } else {
            asm volatile("cp.async.wait_group 0;\n" ::: "memory");
        }
        __syncthreads();
        #pragma unroll
        for (int k = 0; k < 16; k++) {
            float4 a0 = *(const float4*)&As[cur][k][arow];
            float4 a1 = *(const float4*)&As[cur][k][arow + 4];
            float4 b0 = *(const float4*)&Bs[cur][k][bcol];
            float4 b1 = *(const float4*)&Bs[cur][k][bcol + 4];
            float ra[8] = {a0.x, a0.y, a0.z, a0.w, a1.x, a1.y, a1.z, a1.w};
            float rb[8] = {b0.x, b0.y, b0.z, b0.w, b1.x, b1.y, b1.z, b1.w};
            #pragma unroll
            for (int m = 0; m < 8; m++)
                #pragma unroll
                for (int n = 0; n < 8; n++) acc[m][n] += ra[m] * rb[n];
        }
        __syncthreads();
    }

    #pragma unroll
    for (int mi = 0; mi < 8; mi++) {
        float* cp = C + (long)(bm + arow + mi) * HID + bn + bcol;
        *(float4*)cp = make_float4(acc[mi][0], acc[mi][1], acc[mi][2], acc[mi][3]);
        *(float4*)(cp + 4) = make_float4(acc[mi][4], acc[mi][5], acc[mi][6], acc[mi][7]);
    }
}

// ---------------- input prep ------------------------------------------------
// node-major gather, f-padded to 112
__global__ void k_gatherX(const int* __restrict__ x_idx,
                          const float* __restrict__ node_emb) {
    int i = blockIdx.x * 256 + threadIdx.x;
    if (i >= N_NODES * KP1) return;
    int n = i / KP1, f = i - n * KP1;
    g_x[i] = (f < FEAT) ? node_emb[(long)x_idx[n] * FEAT + f] : 0.f;
}

__global__ void k_prep1(const float* __restrict__ W1) {
    int i = blockIdx.x * 256 + threadIdx.x;
    if (i < KP1 * HC) {
        int r = i >> 10;
        g_W1p[i] = (r < FEAT) ? W1[i] : 0.f;
    }
    if (i < N_NODES) { g_cnt[i] = 0; g_cur[i] = 0; }
    if (i < N_GRAPHS * HEADS * HC) g_E[i] = 0.f;
    if (i < N_GRAPHS) g_gcnt[i] = 0.f;
}

__global__ __launch_bounds__(256) void k_w2t(const float* __restrict__ W2) {
    __shared__ float tile[32][33];
    int m0 = blockIdx.x * 32, k0 = blockIdx.y * 32;
    int tx = threadIdx.x, ty = threadIdx.y;
    #pragma unroll
    for (int i = ty; i < 32; i += 8)
        tile[i][tx] = W2[(long)(m0 + i) * HC + k0 + tx];
    __syncthreads();
    #pragma unroll
    for (int i = ty; i < 32; i += 8)
        g_W2T[(long)(k0 + i) * HC + m0 + tx] = tile[tx][i];
}

// ---------------- CSR build ------------------------------------------------
__global__ void k_csr_count(const int* __restrict__ dst) {
    int e = blockIdx.x * blockDim.x + threadIdx.x;
    if (e < N_EDGES) atomicAdd(&g_cnt[dst[e]], 1);
}
__global__ void k_csr_scan() {
    __shared__ int s[1024];
    int tid = threadIdx.x;
    int carry = 0;
    for (int base = 0; base < N_NODES; base += 1024) {
        int i = base + tid;
        int v = (i < N_NODES) ? g_cnt[i] : 0;
        s[tid] = v;
        __syncthreads();
        #pragma unroll
        for (int off = 1; off < 1024; off <<= 1) {
            int t = (tid >= off) ? s[tid - off] : 0;
            __syncthreads();
            s[tid] += t;
            __syncthreads();
        }
        if (i < N_NODES) g_off[i] = carry + s[tid] - v;
        carry += s[1023];
        __syncthreads();
    }
    if (tid == 0) g_off[N_NODES] = carry;
}
__global__ void k_csr_scatter(const int* __restrict__ dst) {
    int e = blockIdx.x * blockDim.x + threadIdx.x;
    if (e < N_EDGES) {
        int d = dst[e];
        int p = atomicAdd(&g_cur[d], 1);
        g_perm[g_off[d] + p] = e;
    }
}

// ---------------- generic fold W·a (src/dst) -> out[k*8+j] -----------------
__global__ void k_fold_v(const float* __restrict__ W,
                         const float* __restrict__ a_s,
                         const float* __restrict__ a_d,
                         float* __restrict__ out, int K) {
    int wid = (blockIdx.x * blockDim.x + threadIdx.x) >> 5;
    int lane = threadIdx.x & 31;
    if (wid >= K * 8) return;
    int k = wid >> 3, j = wid & 7;
    const float* a = (j < 4) ? (a_s + j * HID) : (a_d + (j - 4) * HID);
    int cb = (j & 3) * HID;
    float s = 0.f;
    #pragma unroll
    for (int c = lane; c < HID; c += 32)
        s += W[(long)k * HC + cb + c] * a[c];
    #pragma unroll
    for (int o = 16; o; o >>= 1) s += __shfl_down_sync(0xffffffffu, s, o);
    if (lane == 0) out[k * 8 + j] = s;
}

// layer-1 attention scalars from X directly: als1 = X @ v1
__global__ void k_al1() {
    int n = blockIdx.x * 256 + threadIdx.x;
    if (n >= N_NODES) return;
    float p[8];
    #pragma unroll
    for (int j = 0; j < 8; j++) p[j] = 0.f;
    for (int k = 0; k < FEAT; k++) {
        float x = g_x[(long)n * KP1 + k];
        #pragma unroll
        for (int j = 0; j < 8; j++) p[j] += x * g_v1[k * 8 + j];
    }
    #pragma unroll
    for (int j = 0; j < 4; j++) {
        g_als[n * HEADS + j] = p[j];
        g_ald[n * HEADS + j] = p[j + 4];
    }
}

// layer-2 attention scalars: als2 = F2 @ v  (block per node, smem-staged row)
__global__ __launch_bounds__(256) void k_al2(const float* __restrict__ F2) {
    int n = blockIdx.x;
    __shared__ float row[HC];
    int tid = threadIdx.x;
    for (int i = tid; i < HC; i += 256) row[i] = F2[(long)n * HC + i];
    __syncthreads();
    int w = tid >> 5, lane = tid & 31;
    float s = 0.f;
    for (int k = lane; k < HC; k += 32) s += row[k] * g_v[k * 8 + w];
    #pragma unroll
    for (int o = 16; o; o >>= 1) s += __shfl_down_sync(0xffffffffu, s, o);
    if (lane == 0) {
        if (w < 4) g_als[n * HEADS + w] = s;
        else       g_ald[n * HEADS + (w - 4)] = s;
    }
}

// ---------------- edge-type terms: both layers, one kernel each ------------
__global__ void k_fold_u2(const float* __restrict__ We1,
                          const float* __restrict__ a_edge1,
                          const float* __restrict__ We2,
                          const float* __restrict__ a_edge2) {
    int wid = (blockIdx.x * blockDim.x + threadIdx.x) >> 5;
    int lane = threadIdx.x & 31;
    if (wid >= 2 * HC * HEADS) return;
    int layer = wid >= HC * HEADS;
    int w = wid - layer * HC * HEADS;
    int k = w >> 2, hh = w & 3;
    const float* We = layer ? We2 : We1;
    const float* ae = layer ? a_edge2 : a_edge1;
    float s = 0.f;
    #pragma unroll
    for (int c = lane; c < HID; c += 32)
        s += We[(long)k * HC + hh * HID + c] * ae[hh * HID + c];
    #pragma unroll
    for (int o = 16; o; o >>= 1) s += __shfl_down_sync(0xffffffffu, s, o);
    if (lane == 0) g_u[layer * HC * HEADS + k * HEADS + hh] = s;
}

__global__ void k_alet2(const float* __restrict__ edge_emb) {
    int wid = (blockIdx.x * blockDim.x + threadIdx.x) >> 5;
    int lane = threadIdx.x & 31;
    if (wid >= 2 * N_ETYPES * HEADS) return;
    int layer = wid >= N_ETYPES * HEADS;
    int w = wid - layer * N_ETYPES * HEADS;
    int t = w >> 2, hh = w & 3;
    const float* u = g_u + layer * HC * HEADS;
    float s = 0.f;
    for (int k = lane; k < HC; k += 32)
        s += edge_emb[(long)t * HC + k] * u[k * HEADS + hh];
    #pragma unroll
    for (int o = 16; o; o >>= 1) s += __shfl_down_sync(0xffffffffu, s, o);
    if (lane == 0) g_alet[layer * N_ETYPES * HEADS + t * HEADS + hh] = s;
}

// ---------------- fused logits + 2-pass segment softmax (no max) -----------
__global__ void k_softmax(const int* __restrict__ src,
                          const int* __restrict__ etype, int layer) {
    int idx = blockIdx.x * blockDim.x + threadIdx.x;
    if (idx >= N_NODES * HEADS) return;
    int n = idx >> 2, hh = idx & 3;
    int a = g_off[n], b = g_off[n + 1];
    const float* alet = g_alet + layer * N_ETYPES * HEADS;
    float ald_n = g_ald[n * HEADS + hh];
    float den = 0.f;
    for (int j = a; j < b; j++) {
        int e = g_perm[j];
        float l = g_als[src[e] * HEADS + hh] + ald_n + alet[etype[e] * HEADS + hh];
        l = (l >= 0.f) ? l : 0.2f * l;
        float v = expf(l);
        den += v;
        g_alpha[e * HEADS + hh] = v;
    }
    float inv = 1.f / (den + 1e-16f);
    for (int j = a; j < b; j++)
        g_alpha[g_perm[j] * HEADS + hh] *= inv;
}

// ---------------- layer-1 aggregation in FEAT space ------------------------
// aggX[n][h*112+f] = sum_e alpha[e][h] * X[src_e][f]   (block per node)
__global__ __launch_bounds__(128) void k_aggX(const int* __restrict__ src) {
    int n = blockIdx.x;
    int tid = threadIdx.x;
    float a0 = 0.f, a1 = 0.f, a2 = 0.f, a3 = 0.f;
    int a = g_off[n], b = g_off[n + 1];
    for (int j = a; j < b; j++) {
        int e = g_perm[j];
        float4 al = *(const float4*)&g_alpha[e * 4];
        float x = (tid < KP1) ? g_x[(long)src[e] * KP1 + tid] : 0.f;
        a0 += al.x * x;
        a1 += al.y * x;
        a2 += al.z * x;
        a3 += al.w * x;
    }
    if (tid < KP1) {
        float* op = g_aggX + (long)n * AXW + tid;
        op[0 * KP1] = a0;
        op[1 * KP1] = a1;
        op[2 * KP1] = a2;
        op[3 * KP1] = a3;
    }
}

// ---------------- layer-2: edge-parallel weighted F2 sums ------------------
__global__ __launch_bounds__(256) void k_eagg2(const float* __restrict__ F2,
                                               const int* __restrict__ src,
                                               const int* __restrict__ dst,
                                               const int* __restrict__ batch) {
    __shared__ int    s_src[256];
    __shared__ int    s_g[256];
    __shared__ float4 s_al[256];
    int tid = threadIdx.x;
    int j0 = blockIdx.x * 256;
    {
        int e = g_perm[j0 + tid];
        s_src[tid] = src[e];
        s_g[tid] = batch[dst[e]];
        s_al[tid] = *(const float4*)&g_alpha[e * 4];
    }
    __syncthreads();

    const int c = tid * 4;
    float a0[4] = {0.f, 0.f, 0.f, 0.f};
    float a1[4] = {0.f, 0.f, 0.f, 0.f};
    float a2[4] = {0.f, 0.f, 0.f, 0.f};
    float a3[4] = {0.f, 0.f, 0.f, 0.f};
    int curg = s_g[0];

    auto flush = [&](int g) {
        #pragma unroll
        for (int q = 0; q < 4; q++) {
            if (a0[q] != 0.f) atomicAdd(&g_E[(g * HEADS + 0) * HC + c + q], a0[q]);
            if (a1[q] != 0.f) atomicAdd(&g_E[(g * HEADS + 1) * HC + c + q], a1[q]);
            if (a2[q] != 0.f) atomicAdd(&g_E[(g * HEADS + 2) * HC + c + q], a2[q]);
            if (a3[q] != 0.f) atomicAdd(&g_E[(g * HEADS + 3) * HC + c + q], a3[q]);
            a0[q] = a1[q] = a2[q] = a3[q] = 0.f;
        }
    };

    for (int i = 0; i < 256; i++) {
        int g = s_g[i];
        if (g != curg) { flush(curg); curg = g; }
        float4 f = *(const float4*)(F2 + (long)s_src[i] * HC + c);
        float4 al = s_al[i];
        a0[0] += al.x * f.x; a0[1] += al.x * f.y; a0[2] += al.x * f.z; a0[3] += al.x * f.w;
        a1[0] += al.y * f.x; a1[1] += al.y * f.y; a1[2] += al.y * f.z; a1[3] += al.y * f.w;
        a2[0] += al.z * f.x; a2[1] += al.z * f.y; a2[2] += al.z * f.z; a2[3] += al.z * f.w;
        a3[0] += al.w * f.x; a3[1] += al.w * f.y; a3[2] += al.w * f.z; a3[3] += al.w * f.w;
    }
    flush(curg);
}

// ---------------- per-graph counts / cvec ----------------------------------
__global__ void k_gcnt(const int* __restrict__ batch) {
    int i = blockIdx.x * blockDim.x + threadIdx.x;
    if (i < N_NODES) atomicAdd(&g_gcnt[batch[i]], 1.f);
}

__global__ void k_cvec(const float* __restrict__ b2,
                       const float* __restrict__ projW,
                       const float* __restrict__ projb) {
    int d = threadIdx.x;
    float s = projb[d];
    for (int k = 0; k < HC; k++) s += b2[k] * projW[(long)k * HID + d];
    g_cvec[d] = s;
}

// ---------------- head partials + final reduce/LN --------------------------
__global__ __launch_bounds__(256) void k_partQ() {
    int g = blockIdx.x, h = blockIdx.y;
    int d = threadIdx.x;
    const float* ep = g_E + (long)(g * HEADS + h) * HC;
    const float* qp = g_Q + (long)h * HC * HID;
    float acc = 0.f;
    #pragma unroll 8
    for (int k = 0; k < HC; k++)
        acc += ep[k] * qp[(long)k * HID + d];
    g_part[(long)(g * HEADS + h) * HID + d] = acc;
}

__global__ __launch_bounds__(256) void k_final3(const float* __restrict__ lng,
                                                const float* __restrict__ lnb,
                                                float* __restrict__ out) {
    int g = blockIdx.x;
    int d = threadIdx.x;
    __shared__ float red[256];
    float inv = 1.f / fmaxf(g_gcnt[g], 1.f);
    const float* pp = g_part + (long)g * HEADS * HID + d;
    float acc = pp[0] + pp[HID] + pp[2 * HID] + pp[3 * HID];
    float y = acc * inv + g_cvec[d];
    red[d] = y;
    __syncthreads();
    #pragma unroll
    for (int off = 128; off; off >>= 1) {
        if (d < off) red[d] += red[d + off];
        __syncthreads();
    }
    float mu = red[0] / (float)HID;
    __syncthreads();
    float dv = y - mu;
    red[d] = dv * dv;
    __syncthreads();
    #pragma unroll
    for (int off = 128; off; off >>= 1) {
        if (d < off) red[d] += red[d + off];
        __syncthreads();
    }
    float var = red[0] / (float)HID;
    float r = dv * rsqrtf(var + 1e-5f) * lng[d] + lnb[d];
    out[g * HID + d] = fmaxf(r, 0.f);
}

// ---------------- host orchestration ---------------------------------------
static float* sym(const void* s) {
    void* p = 0;
    cudaGetSymbolAddress(&p, s);
    return (float*)p;
}

extern "C" void kernel_launch(void* const* d_in, const int* in_sizes, int n_in,
                              void* d_out, int out_size) {
    const int*   x_idx    = (const int*)d_in[0];
    const int*   eidx     = (const int*)d_in[1];
    const int*   etype    = (const int*)d_in[2];
    const int*   batch    = (const int*)d_in[3];
    const float* node_emb = (const float*)d_in[4];
    const float* edge_emb = (const float*)d_in[5];
    const float* W1     = (const float*)d_in[6];
    const float* a_src1 = (const float*)d_in[7];
    const float* a_dst1 = (const float*)d_in[8];
    const float* a_edge1= (const float*)d_in[9];
    const float* We1    = (const float*)d_in[10];
    const float* b1     = (const float*)d_in[11];
    const float* W2     = (const float*)d_in[12];
    const float* a_src2 = (const float*)d_in[13];
    const float* a_dst2 = (const float*)d_in[14];
    const float* a_edge2= (const float*)d_in[15];
    const float* We2    = (const float*)d_in[16];
    const float* b2     = (const float*)d_in[17];
    const float* projW  = (const float*)d_in[18];
    const float* projb  = (const float*)d_in[19];
    const float* lng    = (const float*)d_in[20];
    const float* lnb    = (const float*)d_in[21];
    float* out = (float*)d_out;

    const int* src = eidx;
    const int* dst = eidx + N_EDGES;

    float* p_aggX = sym(g_aggX);
    float* p_W1p  = sym(g_W1p);
    float* p_W2T  = sym(g_W2T);
    float* p_feat = sym(g_feat);
    float* p_v    = sym(g_v);
    float* p_v1   = sym(g_v1);

    dim3 fgrid(2, MP / 128, HEADS);            // gemmF: (bn2, bm, head)
    dim3 w2tgrid(HC / 32, HC / 32);
    dim3 qgrid(HID / 128, HC / 128, HEADS);
    dim3 pgrid(N_GRAPHS, HEADS);

    // prep + CSR (csr_scan lands in the ncu probe slot)
    k_prep1<<<(N_GRAPHS * HEADS * HC + 255) / 256, 256>>>(W1);          // 1
    k_gatherX<<<(N_NODES * KP1 + 255) / 256, 256>>>(x_idx, node_emb);   // 2
    k_csr_count<<<(N_EDGES + 255) / 256, 256>>>(dst);                   // 3
    k_csr_scan<<<1, 1024>>>();                                          // 4 <- ncu
    k_csr_scatter<<<(N_EDGES + 255) / 256, 256>>>(dst);                 // 5
    // independent weight prep
    k_w2t<<<w2tgrid, dim3(32, 8)>>>(W2);
    k_qfold<<<qgrid, 256>>>(p_W2T, projW);
    k_fold_v<<<(HC * 8 * 32 + 255) / 256, 256>>>(W2, a_src2, a_dst2, p_v, HC);
    k_fold_v<<<(FEAT * 8 * 32 + 255) / 256, 256>>>(W1, a_src1, a_dst1, p_v1, FEAT);
    k_cvec<<<1, HID>>>(b2, projW, projb);
    k_gcnt<<<(N_NODES + 255) / 256, 256>>>(batch);
    k_fold_u2<<<(2 * HC * HEADS * 32 + 255) / 256, 256>>>(We1, a_edge1, We2, a_edge2);
    k_alet2<<<(2 * N_ETYPES * HEADS * 32 + 255) / 256, 256>>>(edge_emb);
    k_al1<<<(N_NODES + 255) / 256, 256>>>();

    // layer 1: attention -> FEAT-space aggregation -> head-blocked GEMM(+ELU)
    k_softmax<<<(N_NODES * HEADS + 255) / 256, 256>>>(src, etype, 0);
    k_aggX<<<N_NODES, 128>>>(src);
    k_gemmF<<<fgrid, 256>>>(p_aggX, p_W1p, b1, p_feat);
    k_al2<<<N_NODES, 256>>>(p_feat);

    // layer 2 (algebraic path)
    k_softmax<<<(N_NODES * HEADS + 255) / 256, 256>>>(src, etype, 1);
    k_eagg2<<<N_EDGES / 256, 256>>>(p_feat, src, dst, batch);

    // head
    k_partQ<<<pgrid, 256>>>();
    k_final3<<<N_GRAPHS, 256>>>(lng, lnb, out);
}

// round 15
// speedup vs baseline: 1.7131x; 1.1581x over previous
#include <cuda_runtime.h>
#include <math.h>
#include <stdint.h>

#define N_NODES  20000
#define N_EDGES  128000
#define N_GRAPHS 64
#define FEAT     100
#define HID      256
#define HEADS    4
#define HC       1024
#define N_ETYPES 100

#define MP   20096     // N_NODES padded to multiple of 128
#define KP1  112       // FEAT padded to multiple of 16
#define AXW  (HEADS * KP1)   // aggX row width = 448
#define SCB  ((N_NODES + 255) / 256)   // scan blocks = 79

// ---------------- scratch (static device globals; no runtime alloc) --------
__device__ float g_x[N_NODES * KP1];
__device__ float g_W1p[KP1 * HC];
__device__ float g_aggX[MP * AXW];
__device__ float g_feat[MP * HC];
__device__ float g_als[N_NODES * HEADS];
__device__ float g_ald[N_NODES * HEADS];
__device__ float g_u[2 * HC * HEADS];
__device__ float g_alet[2 * N_ETYPES * HEADS];
__device__ float g_alpha[N_EDGES * HEADS];
__device__ int   g_cnt[N_NODES];
__device__ int   g_cur[N_NODES];
__device__ int   g_off[N_NODES + 1];
__device__ int   g_bsum[SCB];
__device__ int   g_boff[SCB];
__device__ int   g_perm[N_EDGES];
__device__ float g_gcnt[N_GRAPHS];
__device__ float g_v[HC * 8];
__device__ float g_v1[FEAT * 8];
__device__ float g_W2T[HC * HC];
__device__ float g_Q[HEADS * HC * HID];
__device__ float g_E[N_GRAPHS * HEADS * HC];
__device__ float g_part[N_GRAPHS * HEADS * HID];
__device__ float g_cvec[HID];

#define CPA16U(dst_u32, src_ptr) \
    asm volatile("cp.async.cg.shared.global [%0], [%1], 16;\n" \
                 :: "r"(dst_u32), "l"(src_ptr))
#define CPA_COMMIT() asm volatile("cp.async.commit_group;\n" ::: "memory")

// ============ head-blocked GEMM: F2[:,h·256+j] = aggX[:,h-slice] @ W1p ======
__global__ __launch_bounds__(256) void k_gemmF(const float* __restrict__ aggX,
                                               const float* __restrict__ W1p,
                                               const float* __restrict__ b1,
                                               float* __restrict__ F2) {
    __shared__ __align__(16) float As[2][16][132];
    __shared__ __align__(16) float Bs[2][16][128];
    const int tid = threadIdx.x;
    const int h = blockIdx.z;
    const int bm = blockIdx.y * 128;
    const int bncol = h * 256 + blockIdx.x * 128;
    const int warp = tid >> 5, lane = tid & 31;
    const int wm = warp & 3, wn = warp >> 2;
    const int ly = lane >> 3, lx = lane & 7;
    const int arow = wm * 32 + ly * 8;
    const int bcol = wn * 64 + lx * 8;

    const int am0 = tid >> 2, akc0 = (tid & 3) * 4;
    const int am1 = (tid + 256) >> 2, akc1 = ((tid + 256) & 3) * 4;

    float acc[8][8];
    #pragma unroll
    for (int m = 0; m < 8; m++)
        #pragma unroll
        for (int n = 0; n < 8; n++) acc[m][n] = 0.f;

    const int S = KP1 / 16;    // 7

    auto load_B = [&](int s, int t) {
        const int k0 = t << 4;
        #pragma unroll
        for (int j = 0; j < 2; j++) {
            int id = tid + j * 256;
            int r = id >> 5, c4 = (id & 31) * 4;
            uint32_t sb = (uint32_t)__cvta_generic_to_shared(&Bs[s][r][c4]);
            CPA16U(sb, W1p + (long)(k0 + r) * HC + bncol + c4);
        }
    };
    auto load_A_regs = [&](float4* ar, int t) {
        const int k0 = t << 4;
        ar[0] = *(const float4*)(aggX + (long)(bm + am0) * AXW + h * KP1 + k0 + akc0);
        ar[1] = *(const float4*)(aggX + (long)(bm + am1) * AXW + h * KP1 + k0 + akc1);
    };
    auto store_A = [&](int s, const float4* ar) {
        As[s][akc0 + 0][am0] = ar[0].x; As[s][akc0 + 1][am0] = ar[0].y;
        As[s][akc0 + 2][am0] = ar[0].z; As[s][akc0 + 3][am0] = ar[0].w;
        As[s][akc1 + 0][am1] = ar[1].x; As[s][akc1 + 1][am1] = ar[1].y;
        As[s][akc1 + 2][am1] = ar[1].z; As[s][akc1 + 3][am1] = ar[1].w;
    };

    {
        float4 ar[2];
        load_A_regs(ar, 0);
        load_B(0, 0);
        CPA_COMMIT();
        store_A(0, ar);
        asm volatile("cp.async.wait_group 0;\n" ::: "memory");
        __syncthreads();
    }

    for (int t = 0; t < S; t++) {
        const int cur = t & 1;
        float4 an[2];
        if (t + 1 < S) {
            load_B(cur ^ 1, t + 1);
            CPA_COMMIT();
            load_A_regs(an, t + 1);
        }
        #pragma unroll
        for (int k = 0; k < 16; k++) {
            float4 a0 = *(const float4*)&As[cur][k][arow];
            float4 a1 = *(const float4*)&As[cur][k][arow + 4];
            float4 b0 = *(const float4*)&Bs[cur][k][bcol];
            float4 b1v = *(const float4*)&Bs[cur][k][bcol + 4];
            float ra[8] = {a0.x, a0.y, a0.z, a0.w, a1.x, a1.y, a1.z, a1.w};
            float rb[8] = {b0.x, b0.y, b0.z, b0.w, b1v.x, b1v.y, b1v.z, b1v.w};
            #pragma unroll
            for (int m = 0; m < 8; m++)
                #pragma unroll
                for (int n = 0; n < 8; n++) acc[m][n] += ra[m] * rb[n];
        }
        if (t + 1 < S) {
            asm volatile("cp.async.wait_group 0;\n" ::: "memory");
            store_A(cur ^ 1, an);
        }
        __syncthreads();
    }

    #pragma unroll
    for (int mi = 0; mi < 8; mi++) {
        float* cp = F2 + (long)(bm + arow + mi) * HC + bncol + bcol;
        float o[8];
        #pragma unroll
        for (int n = 0; n < 8; n++) {
            float x = acc[mi][n] + b1[bncol + bcol + n];
            o[n] = (x > 0.f) ? x : (expf(x) - 1.f);
        }
        *(float4*)cp = make_float4(o[0], o[1], o[2], o[3]);
        *(float4*)(cp + 4) = make_float4(o[4], o[5], o[6], o[7]);
    }
}

// ---- small GEMM for Q_h: C_h[1024x256] = W2T_h^T @ projW_h ----------------
__global__ __launch_bounds__(256) void k_qfold(const float* __restrict__ W2T,
                                               const float* __restrict__ projW) {
    const float* AT = W2T + (long)blockIdx.z * 256 * HC;
    const float* B  = projW + (long)blockIdx.z * 256 * HID;
    float* C = g_Q + (long)blockIdx.z * HC * HID;
    __shared__ __align__(16) float As[2][16][128];
    __shared__ __align__(16) float Bs[2][16][128];
    const int tid = threadIdx.x;
    const int bm = blockIdx.y * 128, bn = blockIdx.x * 128;
    const int warp = tid >> 5, lane = tid & 31;
    const int wm = warp & 3, wn = warp >> 2;
    const int ly = lane >> 3, lx = lane & 7;
    const int arow = wm * 32 + ly * 8;
    const int bcol = wn * 64 + lx * 8;

    float acc[8][8];
    #pragma unroll
    for (int m = 0; m < 8; m++)
        #pragma unroll
        for (int n = 0; n < 8; n++) acc[m][n] = 0.f;

    const int S = 256 >> 4;

    auto load_tiles = [&](int s, int t) {
        const int k0 = t << 4;
        #pragma unroll
        for (int j = 0; j < 2; j++) {
            int id = tid + j * 256;
            int r = id >> 5, c4 = (id & 31) * 4;
            uint32_t sa = (uint32_t)__cvta_generic_to_shared(&As[s][r][c4]);
            CPA16U(sa, AT + (long)(k0 + r) * HC + bm + c4);
            uint32_t sb = (uint32_t)__cvta_generic_to_shared(&Bs[s][r][c4]);
            CPA16U(sb, B + (long)(k0 + r) * HID + bn + c4);
        }
    };

    load_tiles(0, 0);
    CPA_COMMIT();

    for (int t = 0; t < S; t++) {
        const int cur = t & 1;
        if (t + 1 < S) {
            load_tiles((t + 1) & 1, t + 1);
            CPA_COMMIT();
            asm volatile("cp.async.wait_group 1;\n" ::: "memory");
        } else {
            asm volatile("cp.async.wait_group 0;\n" ::: "memory");
        }
        __syncthreads();
        #pragma unroll
        for (int k = 0; k < 16; k++) {
            float4 a0 = *(const float4*)&As[cur][k][arow];
            float4 a1 = *(const float4*)&As[cur][k][arow + 4];
            float4 b0 = *(const float4*)&Bs[cur][k][bcol];
            float4 b1 = *(const float4*)&Bs[cur][k][bcol + 4];
            float ra[8] = {a0.x, a0.y, a0.z, a0.w, a1.x, a1.y, a1.z, a1.w};
            float rb[8] = {b0.x, b0.y, b0.z, b0.w, b1.x, b1.y, b1.z, b1.w};
            #pragma unroll
            for (int m = 0; m < 8; m++)
                #pragma unroll
                for (int n = 0; n < 8; n++) acc[m][n] += ra[m] * rb[n];
        }
        __syncthreads();
    }

    #pragma unroll
    for (int mi = 0; mi < 8; mi++) {
        float* cp = C + (long)(bm + arow + mi) * HID + bn + bcol;
        *(float4*)cp = make_float4(acc[mi][0], acc[mi][1], acc[mi][2], acc[mi][3]);
        *(float4*)(cp + 4) = make_float4(acc[mi][4], acc[mi][5], acc[mi][6], acc[mi][7]);
    }
}

// ---------------- input prep ------------------------------------------------
__global__ void k_gatherX(const int* __restrict__ x_idx,
                          const float* __restrict__ node_emb) {
    int i = blockIdx.x * 256 + threadIdx.x;
    if (i >= N_NODES * KP1) return;
    int n = i / KP1, f = i - n * KP1;
    g_x[i] = (f < FEAT) ? node_emb[(long)x_idx[n] * FEAT + f] : 0.f;
}

__global__ void k_prep1(const float* __restrict__ W1) {
    int i = blockIdx.x * 256 + threadIdx.x;
    if (i < KP1 * HC) {
        int r = i >> 10;
        g_W1p[i] = (r < FEAT) ? W1[i] : 0.f;
    }
    if (i < N_NODES) { g_cnt[i] = 0; g_cur[i] = 0; }
    if (i < N_GRAPHS * HEADS * HC) g_E[i] = 0.f;
    if (i < N_GRAPHS) g_gcnt[i] = 0.f;
}

__global__ __launch_bounds__(256) void k_w2t(const float* __restrict__ W2) {
    __shared__ float tile[32][33];
    int m0 = blockIdx.x * 32, k0 = blockIdx.y * 32;
    int tx = threadIdx.x, ty = threadIdx.y;
    #pragma unroll
    for (int i = ty; i < 32; i += 8)
        tile[i][tx] = W2[(long)(m0 + i) * HC + k0 + tx];
    __syncthreads();
    #pragma unroll
    for (int i = ty; i < 32; i += 8)
        g_W2T[(long)(k0 + i) * HC + m0 + tx] = tile[tx][i];
}

// ---------------- CSR build (decoupled 3-kernel scan) ----------------------
__global__ void k_csr_count(const int* __restrict__ dst) {
    int e = blockIdx.x * blockDim.x + threadIdx.x;
    if (e < N_EDGES) atomicAdd(&g_cnt[dst[e]], 1);
}
// per-block exclusive scan of cnt; block sums out
__global__ __launch_bounds__(256) void k_scanA() {
    __shared__ int s[256];
    int b = blockIdx.x, tid = threadIdx.x;
    int i = b * 256 + tid;
    int v = (i < N_NODES) ? g_cnt[i] : 0;
    s[tid] = v;
    __syncthreads();
    #pragma unroll
    for (int off = 1; off < 256; off <<= 1) {
        int t = (tid >= off) ? s[tid - off] : 0;
        __syncthreads();
        s[tid] += t;
        __syncthreads();
    }
    if (i <= N_NODES) g_off[i] = s[tid] - v;   // local exclusive
    if (tid == 255) g_bsum[b] = s[255];
}
// single small block scans the 79 block sums (exclusive)
__global__ __launch_bounds__(128) void k_scanB() {
    __shared__ int s[128];
    int tid = threadIdx.x;
    int v = (tid < SCB) ? g_bsum[tid] : 0;
    s[tid] = v;
    __syncthreads();
    #pragma unroll
    for (int off = 1; off < 128; off <<= 1) {
        int t = (tid >= off) ? s[tid - off] : 0;
        __syncthreads();
        s[tid] += t;
        __syncthreads();
    }
    if (tid < SCB) g_boff[tid] = s[tid] - v;
}
__global__ void k_scanC() {
    int i = blockIdx.x * 256 + threadIdx.x;
    if (i < N_NODES) g_off[i] += g_boff[i >> 8];
    if (i == 0) g_off[N_NODES] = N_EDGES;
}
__global__ void k_csr_scatter(const int* __restrict__ dst) {
    int e = blockIdx.x * blockDim.x + threadIdx.x;
    if (e < N_EDGES) {
        int d = dst[e];
        int p = atomicAdd(&g_cur[d], 1);
        g_perm[g_off[d] + p] = e;
    }
}

// ---------------- generic fold W·a (src/dst) -> out[k*8+j] -----------------
__global__ void k_fold_v(const float* __restrict__ W,
                         const float* __restrict__ a_s,
                         const float* __restrict__ a_d,
                         float* __restrict__ out, int K) {
    int wid = (blockIdx.x * blockDim.x + threadIdx.x) >> 5;
    int lane = threadIdx.x & 31;
    if (wid >= K * 8) return;
    int k = wid >> 3, j = wid & 7;
    const float* a = (j < 4) ? (a_s + j * HID) : (a_d + (j - 4) * HID);
    int cb = (j & 3) * HID;
    float s = 0.f;
    #pragma unroll
    for (int c = lane; c < HID; c += 32)
        s += W[(long)k * HC + cb + c] * a[c];
    #pragma unroll
    for (int o = 16; o; o >>= 1) s += __shfl_down_sync(0xffffffffu, s, o);
    if (lane == 0) out[k * 8 + j] = s;
}

__global__ void k_al1() {
    int n = blockIdx.x * 256 + threadIdx.x;
    if (n >= N_NODES) return;
    float p[8];
    #pragma unroll
    for (int j = 0; j < 8; j++) p[j] = 0.f;
    for (int k = 0; k < FEAT; k++) {
        float x = g_x[(long)n * KP1 + k];
        #pragma unroll
        for (int j = 0; j < 8; j++) p[j] += x * g_v1[k * 8 + j];
    }
    #pragma unroll
    for (int j = 0; j < 4; j++) {
        g_als[n * HEADS + j] = p[j];
        g_ald[n * HEADS + j] = p[j + 4];
    }
}

__global__ __launch_bounds__(256) void k_al2(const float* __restrict__ F2) {
    int n = blockIdx.x;
    __shared__ float row[HC];
    int tid = threadIdx.x;
    for (int i = tid; i < HC; i += 256) row[i] = F2[(long)n * HC + i];
    __syncthreads();
    int w = tid >> 5, lane = tid & 31;
    float s = 0.f;
    for (int k = lane; k < HC; k += 32) s += row[k] * g_v[k * 8 + w];
    #pragma unroll
    for (int o = 16; o; o >>= 1) s += __shfl_down_sync(0xffffffffu, s, o);
    if (lane == 0) {
        if (w < 4) g_als[n * HEADS + w] = s;
        else       g_ald[n * HEADS + (w - 4)] = s;
    }
}

// ---------------- edge-type terms ------------------------------------------
__global__ void k_fold_u2(const float* __restrict__ We1,
                          const float* __restrict__ a_edge1,
                          const float* __restrict__ We2,
                          const float* __restrict__ a_edge2) {
    int wid = (blockIdx.x * blockDim.x + threadIdx.x) >> 5;
    int lane = threadIdx.x & 31;
    if (wid >= 2 * HC * HEADS) return;
    int layer = wid >= HC * HEADS;
    int w = wid - layer * HC * HEADS;
    int k = w >> 2, hh = w & 3;
    const float* We = layer ? We2 : We1;
    const float* ae = layer ? a_edge2 : a_edge1;
    float s = 0.f;
    #pragma unroll
    for (int c = lane; c < HID; c += 32)
        s += We[(long)k * HC + hh * HID + c] * ae[hh * HID + c];
    #pragma unroll
    for (int o = 16; o; o >>= 1) s += __shfl_down_sync(0xffffffffu, s, o);
    if (lane == 0) g_u[layer * HC * HEADS + k * HEADS + hh] = s;
}

__global__ void k_alet2(const float* __restrict__ edge_emb) {
    int wid = (blockIdx.x * blockDim.x + threadIdx.x) >> 5;
    int lane = threadIdx.x & 31;
    if (wid >= 2 * N_ETYPES * HEADS) return;
    int layer = wid >= N_ETYPES * HEADS;
    int w = wid - layer * N_ETYPES * HEADS;
    int t = w >> 2, hh = w & 3;
    const float* u = g_u + layer * HC * HEADS;
    float s = 0.f;
    for (int k = lane; k < HC; k += 32)
        s += edge_emb[(long)t * HC + k] * u[k * HEADS + hh];
    #pragma unroll
    for (int o = 16; o; o >>= 1) s += __shfl_down_sync(0xffffffffu, s, o);
    if (lane == 0) g_alet[layer * N_ETYPES * HEADS + t * HEADS + hh] = s;
}

// ---------------- fused logits + 2-pass segment softmax --------------------
__global__ void k_softmax(const int* __restrict__ src,
                          const int* __restrict__ etype, int layer) {
    int idx = blockIdx.x * blockDim.x + threadIdx.x;
    if (idx >= N_NODES * HEADS) return;
    int n = idx >> 2, hh = idx & 3;
    int a = g_off[n], b = g_off[n + 1];
    const float* alet = g_alet + layer * N_ETYPES * HEADS;
    float ald_n = g_ald[n * HEADS + hh];
    float den = 0.f;
    for (int j = a; j < b; j++) {
        int e = g_perm[j];
        float l = g_als[src[e] * HEADS + hh] + ald_n + alet[etype[e] * HEADS + hh];
        l = (l >= 0.f) ? l : 0.2f * l;
        float v = expf(l);
        den += v;
        g_alpha[e * HEADS + hh] = v;
    }
    float inv = 1.f / (den + 1e-16f);
    for (int j = a; j < b; j++)
        g_alpha[g_perm[j] * HEADS + hh] *= inv;
}

// ---------------- layer-1 aggregation in FEAT space ------------------------
__global__ __launch_bounds__(128) void k_aggX(const int* __restrict__ src) {
    int n = blockIdx.x;
    int tid = threadIdx.x;
    float a0 = 0.f, a1 = 0.f, a2 = 0.f, a3 = 0.f;
    int a = g_off[n], b = g_off[n + 1];
    for (int j = a; j < b; j++) {
        int e = g_perm[j];
        float4 al = *(const float4*)&g_alpha[e * 4];
        float x = (tid < KP1) ? g_x[(long)src[e] * KP1 + tid] : 0.f;
        a0 += al.x * x;
        a1 += al.y * x;
        a2 += al.z * x;
        a3 += al.w * x;
    }
    if (tid < KP1) {
        float* op = g_aggX + (long)n * AXW + tid;
        op[0 * KP1] = a0;
        op[1 * KP1] = a1;
        op[2 * KP1] = a2;
        op[3 * KP1] = a3;
    }
}

// ---------------- layer-2: edge-parallel weighted F2 sums ------------------
__global__ __launch_bounds__(256) void k_eagg2(const float* __restrict__ F2,
                                               const int* __restrict__ src,
                                               const int* __restrict__ dst,
                                               const int* __restrict__ batch) {
    __shared__ int    s_src[256];
    __shared__ int    s_g[256];
    __shared__ float4 s_al[256];
    int tid = threadIdx.x;
    int j0 = blockIdx.x * 256;
    {
        int e = g_perm[j0 + tid];
        s_src[tid] = src[e];
        s_g[tid] = batch[dst[e]];
        s_al[tid] = *(const float4*)&g_alpha[e * 4];
    }
    __syncthreads();

    const int c = tid * 4;
    float a0[4] = {0.f, 0.f, 0.f, 0.f};
    float a1[4] = {0.f, 0.f, 0.f, 0.f};
    float a2[4] = {0.f, 0.f, 0.f, 0.f};
    float a3[4] = {0.f, 0.f, 0.f, 0.f};
    int curg = s_g[0];

    auto flush = [&](int g) {
        #pragma unroll
        for (int q = 0; q < 4; q++) {
            if (a0[q] != 0.f) atomicAdd(&g_E[(g * HEADS + 0) * HC + c + q], a0[q]);
            if (a1[q] != 0.f) atomicAdd(&g_E[(g * HEADS + 1) * HC + c + q], a1[q]);
            if (a2[q] != 0.f) atomicAdd(&g_E[(g * HEADS + 2) * HC + c + q], a2[q]);
            if (a3[q] != 0.f) atomicAdd(&g_E[(g * HEADS + 3) * HC + c + q], a3[q]);
            a0[q] = a1[q] = a2[q] = a3[q] = 0.f;
        }
    };

    for (int i = 0; i < 256; i++) {
        int g = s_g[i];
        if (g != curg) { flush(curg); curg = g; }
        float4 f = *(const float4*)(F2 + (long)s_src[i] * HC + c);
        float4 al = s_al[i];
        a0[0] += al.x * f.x; a0[1] += al.x * f.y; a0[2] += al.x * f.z; a0[3] += al.x * f.w;
        a1[0] += al.y * f.x; a1[1] += al.y * f.y; a1[2] += al.y * f.z; a1[3] += al.y * f.w;
        a2[0] += al.z * f.x; a2[1] += al.z * f.y; a2[2] += al.z * f.z; a2[3] += al.z * f.w;
        a3[0] += al.w * f.x; a3[1] += al.w * f.y; a3[2] += al.w * f.z; a3[3] += al.w * f.w;
    }
    flush(curg);
}

// ---------------- per-graph counts / cvec ----------------------------------
__global__ void k_gcnt(const int* __restrict__ batch) {
    int i = blockIdx.x * blockDim.x + threadIdx.x;
    if (i < N_NODES) atomicAdd(&g_gcnt[batch[i]], 1.f);
}

__global__ void k_cvec(const float* __restrict__ b2,
                       const float* __restrict__ projW,
                       const float* __restrict__ projb) {
    int d = threadIdx.x;
    float s = projb[d];
    for (int k = 0; k < HC; k++) s += b2[k] * projW[(long)k * HID + d];
    g_cvec[d] = s;
}

// ---------------- head partials + final reduce/LN --------------------------
__global__ __launch_bounds__(256) void k_partQ() {
    int g = blockIdx.x, h = blockIdx.y;
    int d = threadIdx.x;
    const float* ep = g_E + (long)(g * HEADS + h) * HC;
    const float* qp = g_Q + (long)h * HC * HID;
    float acc = 0.f;
    #pragma unroll 8
    for (int k = 0; k < HC; k++)
        acc += ep[k] * qp[(long)k * HID + d];
    g_part[(long)(g * HEADS + h) * HID + d] = acc;
}

__global__ __launch_bounds__(256) void k_final3(const float* __restrict__ lng,
                                                const float* __restrict__ lnb,
                                                float* __restrict__ out) {
    int g = blockIdx.x;
    int d = threadIdx.x;
    __shared__ float red[256];
    float inv = 1.f / fmaxf(g_gcnt[g], 1.f);
    const float* pp = g_part + (long)g * HEADS * HID + d;
    float acc = pp[0] + pp[HID] + pp[2 * HID] + pp[3 * HID];
    float y = acc * inv + g_cvec[d];
    red[d] = y;
    __syncthreads();
    #pragma unroll
    for (int off = 128; off; off >>= 1) {
        if (d < off) red[d] += red[d + off];
        __syncthreads();
    }
    float mu = red[0] / (float)HID;
    __syncthreads();
    float dv = y - mu;
    red[d] = dv * dv;
    __syncthreads();
    #pragma unroll
    for (int off = 128; off; off >>= 1) {
        if (d < off) red[d] += red[d + off];
        __syncthreads();
    }
    float var = red[0] / (float)HID;
    float r = dv * rsqrtf(var + 1e-5f) * lng[d] + lnb[d];
    out[g * HID + d] = fmaxf(r, 0.f);
}

// ---------------- host orchestration ---------------------------------------
static float* sym(const void* s) {
    void* p = 0;
    cudaGetSymbolAddress(&p, s);
    return (float*)p;
}

extern "C" void kernel_launch(void* const* d_in, const int* in_sizes, int n_in,
                              void* d_out, int out_size) {
    const int*   x_idx    = (const int*)d_in[0];
    const int*   eidx     = (const int*)d_in[1];
    const int*   etype    = (const int*)d_in[2];
    const int*   batch    = (const int*)d_in[3];
    const float* node_emb = (const float*)d_in[4];
    const float* edge_emb = (const float*)d_in[5];
    const float* W1     = (const float*)d_in[6];
    const float* a_src1 = (const float*)d_in[7];
    const float* a_dst1 = (const float*)d_in[8];
    const float* a_edge1= (const float*)d_in[9];
    const float* We1    = (const float*)d_in[10];
    const float* b1     = (const float*)d_in[11];
    const float* W2     = (const float*)d_in[12];
    const float* a_src2 = (const float*)d_in[13];
    const float* a_dst2 = (const float*)d_in[14];
    const float* a_edge2= (const float*)d_in[15];
    const float* We2    = (const float*)d_in[16];
    const float* b2     = (const float*)d_in[17];
    const float* projW  = (const float*)d_in[18];
    const float* projb  = (const float*)d_in[19];
    const float* lng    = (const float*)d_in[20];
    const float* lnb    = (const float*)d_in[21];
    float* out = (float*)d_out;

    const int* src = eidx;
    const int* dst = eidx + N_EDGES;

    float* p_aggX = sym(g_aggX);
    float* p_W1p  = sym(g_W1p);
    float* p_W2T  = sym(g_W2T);
    float* p_feat = sym(g_feat);
    float* p_v    = sym(g_v);
    float* p_v1   = sym(g_v1);

    // side stream + events (created once, on the uncaptured correctness call)
    static cudaStream_t s2 = 0;
    static cudaEvent_t evF = 0, evJ = 0;
    if (!s2) {
        cudaStreamCreateWithFlags(&s2, cudaStreamNonBlocking);
        cudaEventCreateWithFlags(&evF, cudaEventDisableTiming);
        cudaEventCreateWithFlags(&evJ, cudaEventDisableTiming);
    }

    dim3 fgrid(2, MP / 128, HEADS);
    dim3 w2tgrid(HC / 32, HC / 32);
    dim3 qgrid(HID / 128, HC / 128, HEADS);
    dim3 pgrid(N_GRAPHS, HEADS);

    // ---- main stream: critical path ----
    k_prep1<<<(N_GRAPHS * HEADS * HC + 255) / 256, 256>>>(W1);          // 1

    // fork side stream after prep (prep zeroes g_E/gcnt used by side work)
    cudaEventRecord(evF, 0);
    cudaStreamWaitEvent(s2, evF, 0);
    k_w2t<<<w2tgrid, dim3(32, 8), 0, s2>>>(W2);
    k_qfold<<<qgrid, 256, 0, s2>>>(p_W2T, projW);
    k_fold_v<<<(HC * 8 * 32 + 255) / 256, 256, 0, s2>>>(W2, a_src2, a_dst2, p_v, HC);
    k_cvec<<<1, HID, 0, s2>>>(b2, projW, projb);
    k_gcnt<<<(N_NODES + 255) / 256, 256, 0, s2>>>(batch);
    cudaEventRecord(evJ, s2);

    k_gatherX<<<(N_NODES * KP1 + 255) / 256, 256>>>(x_idx, node_emb);
    k_csr_count<<<(N_EDGES + 255) / 256, 256>>>(dst);
    k_scanA<<<SCB, 256>>>();
    k_scanB<<<1, 128>>>();
    k_scanC<<<(N_NODES + 255) / 256, 256>>>();
    k_csr_scatter<<<(N_EDGES + 255) / 256, 256>>>(dst);
    k_fold_v<<<(FEAT * 8 * 32 + 255) / 256, 256>>>(W1, a_src1, a_dst1, p_v1, FEAT);
    k_fold_u2<<<(2 * HC * HEADS * 32 + 255) / 256, 256>>>(We1, a_edge1, We2, a_edge2);
    k_alet2<<<(2 * N_ETYPES * HEADS * 32 + 255) / 256, 256>>>(edge_emb);
    k_al1<<<(N_NODES + 255) / 256, 256>>>();

    // layer 1
    k_softmax<<<(N_NODES * HEADS + 255) / 256, 256>>>(src, etype, 0);
    k_aggX<<<N_NODES, 128>>>(src);
    k_gemmF<<<fgrid, 256>>>(p_aggX, p_W1p, b1, p_feat);

    // join side stream (al2 needs g_v; later kernels need Q/cvec/gcnt)
    cudaStreamWaitEvent(0, evJ, 0);
    k_al2<<<N_NODES, 256>>>(p_feat);

    // layer 2
    k_softmax<<<(N_NODES * HEADS + 255) / 256, 256>>>(src, etype, 1);
    k_eagg2<<<N_EDGES / 256, 256>>>(p_feat, src, dst, batch);

    // head
    k_partQ<<<pgrid, 256>>>();
    k_final3<<<N_GRAPHS, 256>>>(lng, lnb, out);
}

// round 16
// speedup vs baseline: 1.8283x; 1.0673x over previous
#include <cuda_runtime.h>
#include <math.h>
#include <stdint.h>

#define N_NODES  20000
#define N_EDGES  128000
#define N_GRAPHS 64
#define FEAT     100
#define HID      256
#define HEADS    4
#define HC       1024
#define N_ETYPES 100

#define MP   20096     // N_NODES padded to multiple of 128
#define KP1  112       // FEAT padded to multiple of 16
#define AXW  (HEADS * KP1)   // aggX row width = 448
#define SCB  ((N_NODES + 255) / 256)   // scan blocks = 79

// ---------------- scratch (static device globals; no runtime alloc) --------
__device__ float g_x[N_NODES * KP1];
__device__ float g_W1p[KP1 * HC];
__device__ float g_aggX[MP * AXW];
__device__ float g_feat[MP * HC];
__device__ float g_als[N_NODES * HEADS];
__device__ float g_ald[N_NODES * HEADS];
__device__ float g_u[2 * HC * HEADS];
__device__ float g_alet[2 * N_ETYPES * HEADS];
__device__ float g_alpha[N_EDGES * HEADS];   // indexed by dst-sorted position j
__device__ int   g_cnt[N_NODES];
__device__ int   g_cur[N_NODES];
__device__ int   g_off[N_NODES + 1];
__device__ int   g_bsum[SCB];
__device__ int   g_boff[SCB];
__device__ int   g_srcp[N_EDGES];            // src in dst-sorted order
__device__ int   g_etp[N_EDGES];             // etype in dst-sorted order
__device__ int   g_gbp[N_EDGES];             // graph of dst in dst-sorted order
__device__ float g_gcnt[N_GRAPHS];
__device__ float g_v[HC * 8];
__device__ float g_v1[FEAT * 8];
__device__ float g_W2T[HC * HC];
__device__ float g_Q[HEADS * HC * HID];
__device__ float g_E[N_GRAPHS * HEADS * HC];
__device__ float g_part[N_GRAPHS * HEADS * HID];
__device__ float g_cvec[HID];

#define CPA16U(dst_u32, src_ptr) \
    asm volatile("cp.async.cg.shared.global [%0], [%1], 16;\n" \
                 :: "r"(dst_u32), "l"(src_ptr))
#define CPA_COMMIT() asm volatile("cp.async.commit_group;\n" ::: "memory")

// ============ head-blocked GEMM: F2[:,h·256+j] = aggX[:,h-slice] @ W1p ======
__global__ __launch_bounds__(256) void k_gemmF(const float* __restrict__ aggX,
                                               const float* __restrict__ W1p,
                                               const float* __restrict__ b1,
                                               float* __restrict__ F2) {
    __shared__ __align__(16) float As[2][16][132];
    __shared__ __align__(16) float Bs[2][16][128];
    const int tid = threadIdx.x;
    const int h = blockIdx.z;
    const int bm = blockIdx.y * 128;
    const int bncol = h * 256 + blockIdx.x * 128;
    const int warp = tid >> 5, lane = tid & 31;
    const int wm = warp & 3, wn = warp >> 2;
    const int ly = lane >> 3, lx = lane & 7;
    const int arow = wm * 32 + ly * 8;
    const int bcol = wn * 64 + lx * 8;

    const int am0 = tid >> 2, akc0 = (tid & 3) * 4;
    const int am1 = (tid + 256) >> 2, akc1 = ((tid + 256) & 3) * 4;

    float acc[8][8];
    #pragma unroll
    for (int m = 0; m < 8; m++)
        #pragma unroll
        for (int n = 0; n < 8; n++) acc[m][n] = 0.f;

    const int S = KP1 / 16;    // 7

    auto load_B = [&](int s, int t) {
        const int k0 = t << 4;
        #pragma unroll
        for (int j = 0; j < 2; j++) {
            int id = tid + j * 256;
            int r = id >> 5, c4 = (id & 31) * 4;
            uint32_t sb = (uint32_t)__cvta_generic_to_shared(&Bs[s][r][c4]);
            CPA16U(sb, W1p + (long)(k0 + r) * HC + bncol + c4);
        }
    };
    auto load_A_regs = [&](float4* ar, int t) {
        const int k0 = t << 4;
        ar[0] = *(const float4*)(aggX + (long)(bm + am0) * AXW + h * KP1 + k0 + akc0);
        ar[1] = *(const float4*)(aggX + (long)(bm + am1) * AXW + h * KP1 + k0 + akc1);
    };
    auto store_A = [&](int s, const float4* ar) {
        As[s][akc0 + 0][am0] = ar[0].x; As[s][akc0 + 1][am0] = ar[0].y;
        As[s][akc0 + 2][am0] = ar[0].z; As[s][akc0 + 3][am0] = ar[0].w;
        As[s][akc1 + 0][am1] = ar[1].x; As[s][akc1 + 1][am1] = ar[1].y;
        As[s][akc1 + 2][am1] = ar[1].z; As[s][akc1 + 3][am1] = ar[1].w;
    };

    {
        float4 ar[2];
        load_A_regs(ar, 0);
        load_B(0, 0);
        CPA_COMMIT();
        store_A(0, ar);
        asm volatile("cp.async.wait_group 0;\n" ::: "memory");
        __syncthreads();
    }

    for (int t = 0; t < S; t++) {
        const int cur = t & 1;
        float4 an[2];
        if (t + 1 < S) {
            load_B(cur ^ 1, t + 1);
            CPA_COMMIT();
            load_A_regs(an, t + 1);
        }
        #pragma unroll
        for (int k = 0; k < 16; k++) {
            float4 a0 = *(const float4*)&As[cur][k][arow];
            float4 a1 = *(const float4*)&As[cur][k][arow + 4];
            float4 b0 = *(const float4*)&Bs[cur][k][bcol];
            float4 b1v = *(const float4*)&Bs[cur][k][bcol + 4];
            float ra[8] = {a0.x, a0.y, a0.z, a0.w, a1.x, a1.y, a1.z, a1.w};
            float rb[8] = {b0.x, b0.y, b0.z, b0.w, b1v.x, b1v.y, b1v.z, b1v.w};
            #pragma unroll
            for (int m = 0; m < 8; m++)
                #pragma unroll
                for (int n = 0; n < 8; n++) acc[m][n] += ra[m] * rb[n];
        }
        if (t + 1 < S) {
            asm volatile("cp.async.wait_group 0;\n" ::: "memory");
            store_A(cur ^ 1, an);
        }
        __syncthreads();
    }

    #pragma unroll
    for (int mi = 0; mi < 8; mi++) {
        float* cp = F2 + (long)(bm + arow + mi) * HC + bncol + bcol;
        float o[8];
        #pragma unroll
        for (int n = 0; n < 8; n++) {
            float x = acc[mi][n] + b1[bncol + bcol + n];
            o[n] = (x > 0.f) ? x : (expf(x) - 1.f);
        }
        *(float4*)cp = make_float4(o[0], o[1], o[2], o[3]);
        *(float4*)(cp + 4) = make_float4(o[4], o[5], o[6], o[7]);
    }
}

// ---- small GEMM for Q_h ---------------------------------------------------
__global__ __launch_bounds__(256) void k_qfold(const float* __restrict__ W2T,
                                               const float* __restrict__ projW) {
    const float* AT = W2T + (long)blockIdx.z * 256 * HC;
    const float* B  = projW + (long)blockIdx.z * 256 * HID;
    float* C = g_Q + (long)blockIdx.z * HC * HID;
    __shared__ __align__(16) float As[2][16][128];
    __shared__ __align__(16) float Bs[2][16][128];
    const int tid = threadIdx.x;
    const int bm = blockIdx.y * 128, bn = blockIdx.x * 128;
    const int warp = tid >> 5, lane = tid & 31;
    const int wm = warp & 3, wn = warp >> 2;
    const int ly = lane >> 3, lx = lane & 7;
    const int arow = wm * 32 + ly * 8;
    const int bcol = wn * 64 + lx * 8;

    float acc[8][8];
    #pragma unroll
    for (int m = 0; m < 8; m++)
        #pragma unroll
        for (int n = 0; n < 8; n++) acc[m][n] = 0.f;

    const int S = 256 >> 4;

    auto load_tiles = [&](int s, int t) {
        const int k0 = t << 4;
        #pragma unroll
        for (int j = 0; j < 2; j++) {
            int id = tid + j * 256;
            int r = id >> 5, c4 = (id & 31) * 4;
            uint32_t sa = (uint32_t)__cvta_generic_to_shared(&As[s][r][c4]);
            CPA16U(sa, AT + (long)(k0 + r) * HC + bm + c4);
            uint32_t sb = (uint32_t)__cvta_generic_to_shared(&Bs[s][r][c4]);
            CPA16U(sb, B + (long)(k0 + r) * HID + bn + c4);
        }
    };

    load_tiles(0, 0);
    CPA_COMMIT();

    for (int t = 0; t < S; t++) {
        const int cur = t & 1;
        if (t + 1 < S) {
            load_tiles((t + 1) & 1, t + 1);
            CPA_COMMIT();
            asm volatile("cp.async.wait_group 1;\n" ::: "memory");
        } else {
            asm volatile("cp.async.wait_group 0;\n" ::: "memory");
        }
        __syncthreads();
        #pragma unroll
        for (int k = 0; k < 16; k++) {
            float4 a0 = *(const float4*)&As[cur][k][arow];
            float4 a1 = *(const float4*)&As[cur][k][arow + 4];
            float4 b0 = *(const float4*)&Bs[cur][k][bcol];
            float4 b1 = *(const float4*)&Bs[cur][k][bcol + 4];
            float ra[8] = {a0.x, a0.y, a0.z, a0.w, a1.x, a1.y, a1.z, a1.w};
            float rb[8] = {b0.x, b0.y, b0.z, b0.w, b1.x, b1.y, b1.z, b1.w};
            #pragma unroll
            for (int m = 0; m < 8; m++)
                #pragma unroll
                for (int n = 0; n < 8; n++) acc[m][n] += ra[m] * rb[n];
        }
        __syncthreads();
    }

    #pragma unroll
    for (int mi = 0; mi < 8; mi++) {
        float* cp = C + (long)(bm + arow + mi) * HID + bn + bcol;
        *(float4*)cp = make_float4(acc[mi][0], acc[mi][1], acc[mi][2], acc[mi][3]);
        *(float4*)(cp + 4) = make_float4(acc[mi][4], acc[mi][5], acc[mi][6], acc[mi][7]);
    }
}

// ---------------- input prep ------------------------------------------------
__global__ void k_gatherX(const int* __restrict__ x_idx,
                          const float* __restrict__ node_emb) {
    int i = blockIdx.x * 256 + threadIdx.x;
    if (i >= N_NODES * KP1) return;
    int n = i / KP1, f = i - n * KP1;
    g_x[i] = (f < FEAT) ? node_emb[(long)x_idx[n] * FEAT + f] : 0.f;
}

__global__ void k_prep1(const float* __restrict__ W1) {
    int i = blockIdx.x * 256 + threadIdx.x;
    if (i < KP1 * HC) {
        int r = i >> 10;
        g_W1p[i] = (r < FEAT) ? W1[i] : 0.f;
    }
    if (i < N_NODES) { g_cnt[i] = 0; g_cur[i] = 0; }
    if (i < N_GRAPHS * HEADS * HC) g_E[i] = 0.f;
    if (i < N_GRAPHS) g_gcnt[i] = 0.f;
}

__global__ __launch_bounds__(256) void k_w2t(const float* __restrict__ W2) {
    __shared__ float tile[32][33];
    int m0 = blockIdx.x * 32, k0 = blockIdx.y * 32;
    int tx = threadIdx.x, ty = threadIdx.y;
    #pragma unroll
    for (int i = ty; i < 32; i += 8)
        tile[i][tx] = W2[(long)(m0 + i) * HC + k0 + tx];
    __syncthreads();
    #pragma unroll
    for (int i = ty; i < 32; i += 8)
        g_W2T[(long)(k0 + i) * HC + m0 + tx] = tile[tx][i];
}

// ---------------- CSR build (decoupled 3-kernel scan) ----------------------
__global__ void k_csr_count(const int* __restrict__ dst) {
    int e = blockIdx.x * blockDim.x + threadIdx.x;
    if (e < N_EDGES) atomicAdd(&g_cnt[dst[e]], 1);
}
__global__ __launch_bounds__(256) void k_scanA() {
    __shared__ int s[256];
    int b = blockIdx.x, tid = threadIdx.x;
    int i = b * 256 + tid;
    int v = (i < N_NODES) ? g_cnt[i] : 0;
    s[tid] = v;
    __syncthreads();
    #pragma unroll
    for (int off = 1; off < 256; off <<= 1) {
        int t = (tid >= off) ? s[tid - off] : 0;
        __syncthreads();
        s[tid] += t;
        __syncthreads();
    }
    if (i <= N_NODES) g_off[i] = s[tid] - v;
    if (tid == 255) g_bsum[b] = s[255];
}
__global__ __launch_bounds__(128) void k_scanB() {
    __shared__ int s[128];
    int tid = threadIdx.x;
    int v = (tid < SCB) ? g_bsum[tid] : 0;
    s[tid] = v;
    __syncthreads();
    #pragma unroll
    for (int off = 1; off < 128; off <<= 1) {
        int t = (tid >= off) ? s[tid - off] : 0;
        __syncthreads();
        s[tid] += t;
        __syncthreads();
    }
    if (tid < SCB) g_boff[tid] = s[tid] - v;
}
__global__ void k_scanC() {
    int i = blockIdx.x * 256 + threadIdx.x;
    if (i < N_NODES) g_off[i] += g_boff[i >> 8];
    if (i == 0) g_off[N_NODES] = N_EDGES;
}
// scatter + materialize dst-sorted edge arrays
__global__ void k_csr_scatter(const int* __restrict__ src,
                              const int* __restrict__ dst,
                              const int* __restrict__ etype,
                              const int* __restrict__ batch) {
    int e = blockIdx.x * blockDim.x + threadIdx.x;
    if (e < N_EDGES) {
        int d = dst[e];
        int p = atomicAdd(&g_cur[d], 1);
        int pos = g_off[d] + p;
        g_srcp[pos] = src[e];
        g_etp[pos]  = etype[e];
        g_gbp[pos]  = batch[d];
    }
}

// ---------------- generic fold W·a (src/dst) -> out[k*8+j] -----------------
__global__ void k_fold_v(const float* __restrict__ W,
                         const float* __restrict__ a_s,
                         const float* __restrict__ a_d,
                         float* __restrict__ out, int K) {
    int wid = (blockIdx.x * blockDim.x + threadIdx.x) >> 5;
    int lane = threadIdx.x & 31;
    if (wid >= K * 8) return;
    int k = wid >> 3, j = wid & 7;
    const float* a = (j < 4) ? (a_s + j * HID) : (a_d + (j - 4) * HID);
    int cb = (j & 3) * HID;
    float s = 0.f;
    #pragma unroll
    for (int c = lane; c < HID; c += 32)
        s += W[(long)k * HC + cb + c] * a[c];
    #pragma unroll
    for (int o = 16; o; o >>= 1) s += __shfl_down_sync(0xffffffffu, s, o);
    if (lane == 0) out[k * 8 + j] = s;
}

__global__ void k_al1() {
    int n = blockIdx.x * 256 + threadIdx.x;
    if (n >= N_NODES) return;
    float p[8];
    #pragma unroll
    for (int j = 0; j < 8; j++) p[j] = 0.f;
    for (int k = 0; k < FEAT; k++) {
        float x = g_x[(long)n * KP1 + k];
        #pragma unroll
        for (int j = 0; j < 8; j++) p[j] += x * g_v1[k * 8 + j];
    }
    #pragma unroll
    for (int j = 0; j < 4; j++) {
        g_als[n * HEADS + j] = p[j];
        g_ald[n * HEADS + j] = p[j + 4];
    }
}

__global__ __launch_bounds__(256) void k_al2(const float* __restrict__ F2) {
    int n = blockIdx.x;
    __shared__ float row[HC];
    int tid = threadIdx.x;
    for (int i = tid; i < HC; i += 256) row[i] = F2[(long)n * HC + i];
    __syncthreads();
    int w = tid >> 5, lane = tid & 31;
    float s = 0.f;
    for (int k = lane; k < HC; k += 32) s += row[k] * g_v[k * 8 + w];
    #pragma unroll
    for (int o = 16; o; o >>= 1) s += __shfl_down_sync(0xffffffffu, s, o);
    if (lane == 0) {
        if (w < 4) g_als[n * HEADS + w] = s;
        else       g_ald[n * HEADS + (w - 4)] = s;
    }
}

// ---------------- edge-type terms ------------------------------------------
__global__ void k_fold_u2(const float* __restrict__ We1,
                          const float* __restrict__ a_edge1,
                          const float* __restrict__ We2,
                          const float* __restrict__ a_edge2) {
    int wid = (blockIdx.x * blockDim.x + threadIdx.x) >> 5;
    int lane = threadIdx.x & 31;
    if (wid >= 2 * HC * HEADS) return;
    int layer = wid >= HC * HEADS;
    int w = wid - layer * HC * HEADS;
    int k = w >> 2, hh = w & 3;
    const float* We = layer ? We2 : We1;
    const float* ae = layer ? a_edge2 : a_edge1;
    float s = 0.f;
    #pragma unroll
    for (int c = lane; c < HID; c += 32)
        s += We[(long)k * HC + hh * HID + c] * ae[hh * HID + c];
    #pragma unroll
    for (int o = 16; o; o >>= 1) s += __shfl_down_sync(0xffffffffu, s, o);
    if (lane == 0) g_u[layer * HC * HEADS + k * HEADS + hh] = s;
}

__global__ void k_alet2(const float* __restrict__ edge_emb) {
    int wid = (blockIdx.x * blockDim.x + threadIdx.x) >> 5;
    int lane = threadIdx.x & 31;
    if (wid >= 2 * N_ETYPES * HEADS) return;
    int layer = wid >= N_ETYPES * HEADS;
    int w = wid - layer * N_ETYPES * HEADS;
    int t = w >> 2, hh = w & 3;
    const float* u = g_u + layer * HC * HEADS;
    float s = 0.f;
    for (int k = lane; k < HC; k += 32)
        s += edge_emb[(long)t * HC + k] * u[k * HEADS + hh];
    #pragma unroll
    for (int o = 16; o; o >>= 1) s += __shfl_down_sync(0xffffffffu, s, o);
    if (lane == 0) g_alet[layer * N_ETYPES * HEADS + t * HEADS + hh] = s;
}

// ---------------- fused logits + segment softmax (contiguous arrays) -------
__global__ void k_softmax(const int* __restrict__, int layer) {
    int idx = blockIdx.x * blockDim.x + threadIdx.x;
    if (idx >= N_NODES * HEADS) return;
    int n = idx >> 2, hh = idx & 3;
    int a = g_off[n], b = g_off[n + 1];
    const float* alet = g_alet + layer * N_ETYPES * HEADS;
    float ald_n = g_ald[n * HEADS + hh];
    float den = 0.f;
    for (int j = a; j < b; j++) {
        float l = g_als[g_srcp[j] * HEADS + hh] + ald_n +
                  alet[g_etp[j] * HEADS + hh];
        l = (l >= 0.f) ? l : 0.2f * l;
        float v = expf(l);
        den += v;
        g_alpha[j * HEADS + hh] = v;
    }
    float inv = 1.f / (den + 1e-16f);
    for (int j = a; j < b; j++)
        g_alpha[j * HEADS + hh] *= inv;
}

// ---------------- layer-1 aggregation in FEAT space ------------------------
__global__ __launch_bounds__(128) void k_aggX() {
    int n = blockIdx.x;
    int tid = threadIdx.x;
    float a0 = 0.f, a1 = 0.f, a2 = 0.f, a3 = 0.f;
    int a = g_off[n], b = g_off[n + 1];
    for (int j = a; j < b; j++) {
        float4 al = *(const float4*)&g_alpha[j * 4];
        float x = (tid < KP1) ? g_x[(long)g_srcp[j] * KP1 + tid] : 0.f;
        a0 += al.x * x;
        a1 += al.y * x;
        a2 += al.z * x;
        a3 += al.w * x;
    }
    if (tid < KP1) {
        float* op = g_aggX + (long)n * AXW + tid;
        op[0 * KP1] = a0;
        op[1 * KP1] = a1;
        op[2 * KP1] = a2;
        op[3 * KP1] = a3;
    }
}

// ---------------- layer-2: edge-parallel weighted F2 sums ------------------
__global__ __launch_bounds__(256) void k_eagg2(const float* __restrict__ F2) {
    __shared__ int    s_src[256];
    __shared__ int    s_g[256];
    __shared__ float4 s_al[256];
    int tid = threadIdx.x;
    int j0 = blockIdx.x * 256;
    s_src[tid] = g_srcp[j0 + tid];
    s_g[tid]   = g_gbp[j0 + tid];
    s_al[tid]  = *(const float4*)&g_alpha[(j0 + tid) * 4];
    __syncthreads();

    const int c = tid * 4;
    float a0[4] = {0.f, 0.f, 0.f, 0.f};
    float a1[4] = {0.f, 0.f, 0.f, 0.f};
    float a2[4] = {0.f, 0.f, 0.f, 0.f};
    float a3[4] = {0.f, 0.f, 0.f, 0.f};
    int curg = s_g[0];

    auto flush = [&](int g) {
        #pragma unroll
        for (int q = 0; q < 4; q++) {
            if (a0[q] != 0.f) atomicAdd(&g_E[(g * HEADS + 0) * HC + c + q], a0[q]);
            if (a1[q] != 0.f) atomicAdd(&g_E[(g * HEADS + 1) * HC + c + q], a1[q]);
            if (a2[q] != 0.f) atomicAdd(&g_E[(g * HEADS + 2) * HC + c + q], a2[q]);
            if (a3[q] != 0.f) atomicAdd(&g_E[(g * HEADS + 3) * HC + c + q], a3[q]);
            a0[q] = a1[q] = a2[q] = a3[q] = 0.f;
        }
    };

    for (int i = 0; i < 256; i++) {
        int g = s_g[i];
        if (g != curg) { flush(curg); curg = g; }
        float4 f = *(const float4*)(F2 + (long)s_src[i] * HC + c);
        float4 al = s_al[i];
        a0[0] += al.x * f.x; a0[1] += al.x * f.y; a0[2] += al.x * f.z; a0[3] += al.x * f.w;
        a1[0] += al.y * f.x; a1[1] += al.y * f.y; a1[2] += al.y * f.z; a1[3] += al.y * f.w;
        a2[0] += al.z * f.x; a2[1] += al.z * f.y; a2[2] += al.z * f.z; a2[3] += al.z * f.w;
        a3[0] += al.w * f.x; a3[1] += al.w * f.y; a3[2] += al.w * f.z; a3[3] += al.w * f.w;
    }
    flush(curg);
}

// ---------------- per-graph counts / cvec ----------------------------------
__global__ void k_gcnt(const int* __restrict__ batch) {
    int i = blockIdx.x * blockDim.x + threadIdx.x;
    if (i < N_NODES) atomicAdd(&g_gcnt[batch[i]], 1.f);
}

__global__ void k_cvec(const float* __restrict__ b2,
                       const float* __restrict__ projW,
                       const float* __restrict__ projb) {
    int d = threadIdx.x;
    float s = projb[d];
    for (int k = 0; k < HC; k++) s += b2[k] * projW[(long)k * HID + d];
    g_cvec[d] = s;
}

// ---------------- head partials + final reduce/LN --------------------------
__global__ __launch_bounds__(256) void k_partQ() {
    int g = blockIdx.x, h = blockIdx.y;
    int d = threadIdx.x;
    const float* ep = g_E + (long)(g * HEADS + h) * HC;
    const float* qp = g_Q + (long)h * HC * HID;
    float acc = 0.f;
    #pragma unroll 8
    for (int k = 0; k < HC; k++)
        acc += ep[k] * qp[(long)k * HID + d];
    g_part[(long)(g * HEADS + h) * HID + d] = acc;
}

__global__ __launch_bounds__(256) void k_final3(const float* __restrict__ lng,
                                                const float* __restrict__ lnb,
                                                float* __restrict__ out) {
    int g = blockIdx.x;
    int d = threadIdx.x;
    __shared__ float red[256];
    float inv = 1.f / fmaxf(g_gcnt[g], 1.f);
    const float* pp = g_part + (long)g * HEADS * HID + d;
    float acc = pp[0] + pp[HID] + pp[2 * HID] + pp[3 * HID];
    float y = acc * inv + g_cvec[d];
    red[d] = y;
    __syncthreads();
    #pragma unroll
    for (int off = 128; off; off >>= 1) {
        if (d < off) red[d] += red[d + off];
        __syncthreads();
    }
    float mu = red[0] / (float)HID;
    __syncthreads();
    float dv = y - mu;
    red[d] = dv * dv;
    __syncthreads();
    #pragma unroll
    for (int off = 128; off; off >>= 1) {
        if (d < off) red[d] += red[d + off];
        __syncthreads();
    }
    float var = red[0] / (float)HID;
    float r = dv * rsqrtf(var + 1e-5f) * lng[d] + lnb[d];
    out[g * HID + d] = fmaxf(r, 0.f);
}

// ---------------- host orchestration ---------------------------------------
static float* sym(const void* s) {
    void* p = 0;
    cudaGetSymbolAddress(&p, s);
    return (float*)p;
}

extern "C" void kernel_launch(void* const* d_in, const int* in_sizes, int n_in,
                              void* d_out, int out_size) {
    const int*   x_idx    = (const int*)d_in[0];
    const int*   eidx     = (const int*)d_in[1];
    const int*   etype    = (const int*)d_in[2];
    const int*   batch    = (const int*)d_in[3];
    const float* node_emb = (const float*)d_in[4];
    const float* edge_emb = (const float*)d_in[5];
    const float* W1     = (const float*)d_in[6];
    const float* a_src1 = (const float*)d_in[7];
    const float* a_dst1 = (const float*)d_in[8];
    const float* a_edge1= (const float*)d_in[9];
    const float* We1    = (const float*)d_in[10];
    const float* b1     = (const float*)d_in[11];
    const float* W2     = (const float*)d_in[12];
    const float* a_src2 = (const float*)d_in[13];
    const float* a_dst2 = (const float*)d_in[14];
    const float* a_edge2= (const float*)d_in[15];
    const float* We2    = (const float*)d_in[16];
    const float* b2     = (const float*)d_in[17];
    const float* projW  = (const float*)d_in[18];
    const float* projb  = (const float*)d_in[19];
    const float* lng    = (const float*)d_in[20];
    const float* lnb    = (const float*)d_in[21];
    float* out = (float*)d_out;

    const int* src = eidx;
    const int* dst = eidx + N_EDGES;

    float* p_aggX = sym(g_aggX);
    float* p_W1p  = sym(g_W1p);
    float* p_W2T  = sym(g_W2T);
    float* p_feat = sym(g_feat);
    float* p_v    = sym(g_v);
    float* p_v1   = sym(g_v1);

    static cudaStream_t s2 = 0;
    static cudaEvent_t evF = 0, evJ = 0;
    if (!s2) {
        cudaStreamCreateWithFlags(&s2, cudaStreamNonBlocking);
        cudaEventCreateWithFlags(&evF, cudaEventDisableTiming);
        cudaEventCreateWithFlags(&evJ, cudaEventDisableTiming);
    }

    dim3 fgrid(2, MP / 128, HEADS);
    dim3 w2tgrid(HC / 32, HC / 32);
    dim3 qgrid(HID / 128, HC / 128, HEADS);
    dim3 pgrid(N_GRAPHS, HEADS);

    // ---- main stream: critical path ----
    k_prep1<<<(N_GRAPHS * HEADS * HC + 255) / 256, 256>>>(W1);

    // fork side stream
    cudaEventRecord(evF, 0);
    cudaStreamWaitEvent(s2, evF, 0);
    k_w2t<<<w2tgrid, dim3(32, 8), 0, s2>>>(W2);
    k_qfold<<<qgrid, 256, 0, s2>>>(p_W2T, projW);
    k_fold_v<<<(HC * 8 * 32 + 255) / 256, 256, 0, s2>>>(W2, a_src2, a_dst2, p_v, HC);
    k_cvec<<<1, HID, 0, s2>>>(b2, projW, projb);
    k_gcnt<<<(N_NODES + 255) / 256, 256, 0, s2>>>(batch);
    cudaEventRecord(evJ, s2);

    k_gatherX<<<(N_NODES * KP1 + 255) / 256, 256>>>(x_idx, node_emb);
    k_csr_count<<<(N_EDGES + 255) / 256, 256>>>(dst);
    k_scanA<<<SCB, 256>>>();
    k_scanB<<<1, 128>>>();
    k_scanC<<<(N_NODES + 255) / 256, 256>>>();
    k_csr_scatter<<<(N_EDGES + 255) / 256, 256>>>(src, dst, etype, batch);
    k_fold_v<<<(FEAT * 8 * 32 + 255) / 256, 256>>>(W1, a_src1, a_dst1, p_v1, FEAT);
    k_fold_u2<<<(2 * HC * HEADS * 32 + 255) / 256, 256>>>(We1, a_edge1, We2, a_edge2);
    k_alet2<<<(2 * N_ETYPES * HEADS * 32 + 255) / 256, 256>>>(edge_emb);
    k_al1<<<(N_NODES + 255) / 256, 256>>>();

    // layer 1
    k_softmax<<<(N_NODES * HEADS + 255) / 256, 256>>>(src, 0);
    k_aggX<<<N_NODES, 128>>>();
    k_gemmF<<<fgrid, 256>>>(p_aggX, p_W1p, b1, p_feat);

    // join side stream
    cudaStreamWaitEvent(0, evJ, 0);
    k_al2<<<N_NODES, 256>>>(p_feat);

    // layer 2
    k_softmax<<<(N_NODES * HEADS + 255) / 256, 256>>>(src, 1);
    k_eagg2<<<N_EDGES / 256, 256>>>(p_feat);

    // head
    k_partQ<<<pgrid, 256>>>();
    k_final3<<<N_GRAPHS, 256>>>(lng, lnb, out);
}

// round 17
// speedup vs baseline: 2.1253x; 1.1624x over previous
#include <cuda_runtime.h>
#include <math.h>
#include <stdint.h>

#define N_NODES  20000
#define N_EDGES  128000
#define N_GRAPHS 64
#define FEAT     100
#define HID      256
#define HEADS    4
#define HC       1024
#define N_ETYPES 100

#define MP   20096     // N_NODES padded to multiple of 128
#define KP1  112       // FEAT padded to multiple of 16
#define AXW  (HEADS * KP1)   // aggX row width = 448
#define SCB  ((N_NODES + 255) / 256)   // scan blocks = 79

// ---------------- scratch (static device globals; no runtime alloc) --------
__device__ float g_x[N_NODES * KP1];
__device__ float g_W1p[KP1 * HC];
__device__ float g_aggX[MP * AXW];
__device__ float g_feat[MP * HC];
__device__ float g_als[N_NODES * HEADS];
__device__ float g_ald[N_NODES * HEADS];
__device__ float g_u[2 * HC * HEADS];
__device__ float g_alet[2 * N_ETYPES * HEADS];
__device__ float g_alpha[N_EDGES * HEADS];   // dst-sorted position j
__device__ int   g_cnt[N_NODES];
__device__ int   g_cur[N_NODES];
__device__ int   g_off[N_NODES + 1];
__device__ int   g_bsum[SCB];
__device__ int   g_boff[SCB];
__device__ int   g_srcp[N_EDGES];            // src in dst-sorted order
__device__ int   g_dstp[N_EDGES];            // dst in dst-sorted order
__device__ int   g_etp[N_EDGES];             // etype in dst-sorted order
__device__ int   g_gbp[N_EDGES];             // graph of dst in dst-sorted order
__device__ float g_gcnt[N_GRAPHS];
__device__ float g_v[HC * 8];
__device__ float g_v1[FEAT * 8];
__device__ float g_W2T[HC * HC];
__device__ float g_Q[HEADS * HC * HID];
__device__ float g_E[N_GRAPHS * HEADS * HC];
__device__ float g_part[N_GRAPHS * HEADS * HID];
__device__ float g_cvec[HID];

#define CPA16U(dst_u32, src_ptr) \
    asm volatile("cp.async.cg.shared.global [%0], [%1], 16;\n" \
                 :: "r"(dst_u32), "l"(src_ptr))
#define CPA_COMMIT() asm volatile("cp.async.commit_group;\n" ::: "memory")

// ============ head-blocked GEMM: F2[:,h·256+j] = aggX[:,h-slice] @ W1p ======
__global__ __launch_bounds__(256) void k_gemmF(const float* __restrict__ aggX,
                                               const float* __restrict__ W1p,
                                               const float* __restrict__ b1,
                                               float* __restrict__ F2) {
    __shared__ __align__(16) float As[2][16][132];
    __shared__ __align__(16) float Bs[2][16][128];
    const int tid = threadIdx.x;
    const int h = blockIdx.z;
    const int bm = blockIdx.y * 128;
    const int bncol = h * 256 + blockIdx.x * 128;
    const int warp = tid >> 5, lane = tid & 31;
    const int wm = warp & 3, wn = warp >> 2;
    const int ly = lane >> 3, lx = lane & 7;
    const int arow = wm * 32 + ly * 8;
    const int bcol = wn * 64 + lx * 8;

    const int am0 = tid >> 2, akc0 = (tid & 3) * 4;
    const int am1 = (tid + 256) >> 2, akc1 = ((tid + 256) & 3) * 4;

    float acc[8][8];
    #pragma unroll
    for (int m = 0; m < 8; m++)
        #pragma unroll
        for (int n = 0; n < 8; n++) acc[m][n] = 0.f;

    const int S = KP1 / 16;    // 7

    auto load_B = [&](int s, int t) {
        const int k0 = t << 4;
        #pragma unroll
        for (int j = 0; j < 2; j++) {
            int id = tid + j * 256;
            int r = id >> 5, c4 = (id & 31) * 4;
            uint32_t sb = (uint32_t)__cvta_generic_to_shared(&Bs[s][r][c4]);
            CPA16U(sb, W1p + (long)(k0 + r) * HC + bncol + c4);
        }
    };
    auto load_A_regs = [&](float4* ar, int t) {
        const int k0 = t << 4;
        ar[0] = *(const float4*)(aggX + (long)(bm + am0) * AXW + h * KP1 + k0 + akc0);
        ar[1] = *(const float4*)(aggX + (long)(bm + am1) * AXW + h * KP1 + k0 + akc1);
    };
    auto store_A = [&](int s, const float4* ar) {
        As[s][akc0 + 0][am0] = ar[0].x; As[s][akc0 + 1][am0] = ar[0].y;
        As[s][akc0 + 2][am0] = ar[0].z; As[s][akc0 + 3][am0] = ar[0].w;
        As[s][akc1 + 0][am1] = ar[1].x; As[s][akc1 + 1][am1] = ar[1].y;
        As[s][akc1 + 2][am1] = ar[1].z; As[s][akc1 + 3][am1] = ar[1].w;
    };

    {
        float4 ar[2];
        load_A_regs(ar, 0);
        load_B(0, 0);
        CPA_COMMIT();
        store_A(0, ar);
        asm volatile("cp.async.wait_group 0;\n" ::: "memory");
        __syncthreads();
    }

    for (int t = 0; t < S; t++) {
        const int cur = t & 1;
        float4 an[2];
        if (t + 1 < S) {
            load_B(cur ^ 1, t + 1);
            CPA_COMMIT();
            load_A_regs(an, t + 1);
        }
        #pragma unroll
        for (int k = 0; k < 16; k++) {
            float4 a0 = *(const float4*)&As[cur][k][arow];
            float4 a1 = *(const float4*)&As[cur][k][arow + 4];
            float4 b0 = *(const float4*)&Bs[cur][k][bcol];
            float4 b1v = *(const float4*)&Bs[cur][k][bcol + 4];
            float ra[8] = {a0.x, a0.y, a0.z, a0.w, a1.x, a1.y, a1.z, a1.w};
            float rb[8] = {b0.x, b0.y, b0.z, b0.w, b1v.x, b1v.y, b1v.z, b1v.w};
            #pragma unroll
            for (int m = 0; m < 8; m++)
                #pragma unroll
                for (int n = 0; n < 8; n++) acc[m][n] += ra[m] * rb[n];
        }
        if (t + 1 < S) {
            asm volatile("cp.async.wait_group 0;\n" ::: "memory");
            store_A(cur ^ 1, an);
        }
        __syncthreads();
    }

    #pragma unroll
    for (int mi = 0; mi < 8; mi++) {
        float* cp = F2 + (long)(bm + arow + mi) * HC + bncol + bcol;
        float o[8];
        #pragma unroll
        for (int n = 0; n < 8; n++) {
            float x = acc[mi][n] + b1[bncol + bcol + n];
            o[n] = (x > 0.f) ? x : (expf(x) - 1.f);
        }
        *(float4*)cp = make_float4(o[0], o[1], o[2], o[3]);
        *(float4*)(cp + 4) = make_float4(o[4], o[5], o[6], o[7]);
    }
}

// ---- small GEMM for Q_h ---------------------------------------------------
__global__ __launch_bounds__(256) void k_qfold(const float* __restrict__ W2T,
                                               const float* __restrict__ projW) {
    const float* AT = W2T + (long)blockIdx.z * 256 * HC;
    const float* B  = projW + (long)blockIdx.z * 256 * HID;
    float* C = g_Q + (long)blockIdx.z * HC * HID;
    __shared__ __align__(16) float As[2][16][128];
    __shared__ __align__(16) float Bs[2][16][128];
    const int tid = threadIdx.x;
    const int bm = blockIdx.y * 128, bn = blockIdx.x * 128;
    const int warp = tid >> 5, lane = tid & 31;
    const int wm = warp & 3, wn = warp >> 2;
    const int ly = lane >> 3, lx = lane & 7;
    const int arow = wm * 32 + ly * 8;
    const int bcol = wn * 64 + lx * 8;

    float acc[8][8];
    #pragma unroll
    for (int m = 0; m < 8; m++)
        #pragma unroll
        for (int n = 0; n < 8; n++) acc[m][n] = 0.f;

    const int S = 256 >> 4;

    auto load_tiles = [&](int s, int t) {
        const int k0 = t << 4;
        #pragma unroll
        for (int j = 0; j < 2; j++) {
            int id = tid + j * 256;
            int r = id >> 5, c4 = (id & 31) * 4;
            uint32_t sa = (uint32_t)__cvta_generic_to_shared(&As[s][r][c4]);
            CPA16U(sa, AT + (long)(k0 + r) * HC + bm + c4);
            uint32_t sb = (uint32_t)__cvta_generic_to_shared(&Bs[s][r][c4]);
            CPA16U(sb, B + (long)(k0 + r) * HID + bn + c4);
        }
    };

    load_tiles(0, 0);
    CPA_COMMIT();

    for (int t = 0; t < S; t++) {
        const int cur = t & 1;
        if (t + 1 < S) {
            load_tiles((t + 1) & 1, t + 1);
            CPA_COMMIT();
            asm volatile("cp.async.wait_group 1;\n" ::: "memory");
        } else {
            asm volatile("cp.async.wait_group 0;\n" ::: "memory");
        }
        __syncthreads();
        #pragma unroll
        for (int k = 0; k < 16; k++) {
            float4 a0 = *(const float4*)&As[cur][k][arow];
            float4 a1 = *(const float4*)&As[cur][k][arow + 4];
            float4 b0 = *(const float4*)&Bs[cur][k][bcol];
            float4 b1 = *(const float4*)&Bs[cur][k][bcol + 4];
            float ra[8] = {a0.x, a0.y, a0.z, a0.w, a1.x, a1.y, a1.z, a1.w};
            float rb[8] = {b0.x, b0.y, b0.z, b0.w, b1.x, b1.y, b1.z, b1.w};
            #pragma unroll
            for (int m = 0; m < 8; m++)
                #pragma unroll
                for (int n = 0; n < 8; n++) acc[m][n] += ra[m] * rb[n];
        }
        __syncthreads();
    }

    #pragma unroll
    for (int mi = 0; mi < 8; mi++) {
        float* cp = C + (long)(bm + arow + mi) * HID + bn + bcol;
        *(float4*)cp = make_float4(acc[mi][0], acc[mi][1], acc[mi][2], acc[mi][3]);
        *(float4*)(cp + 4) = make_float4(acc[mi][4], acc[mi][5], acc[mi][6], acc[mi][7]);
    }
}

// ---------------- input prep ------------------------------------------------
__global__ void k_gatherX(const int* __restrict__ x_idx,
                          const float* __restrict__ node_emb) {
    int i = blockIdx.x * 256 + threadIdx.x;
    if (i >= N_NODES * KP1) return;
    int n = i / KP1, f = i - n * KP1;
    g_x[i] = (f < FEAT) ? node_emb[(long)x_idx[n] * FEAT + f] : 0.f;
}

__global__ void k_prep1(const float* __restrict__ W1) {
    int i = blockIdx.x * 256 + threadIdx.x;
    if (i < KP1 * HC) {
        int r = i >> 10;
        g_W1p[i] = (r < FEAT) ? W1[i] : 0.f;
    }
    if (i < N_NODES) { g_cnt[i] = 0; g_cur[i] = 0; }
    if (i < N_GRAPHS * HEADS * HC) g_E[i] = 0.f;
    if (i < N_GRAPHS * HEADS * HID) g_part[i] = 0.f;
    if (i < N_GRAPHS) g_gcnt[i] = 0.f;
}

__global__ __launch_bounds__(256) void k_w2t(const float* __restrict__ W2) {
    __shared__ float tile[32][33];
    int m0 = blockIdx.x * 32, k0 = blockIdx.y * 32;
    int tx = threadIdx.x, ty = threadIdx.y;
    #pragma unroll
    for (int i = ty; i < 32; i += 8)
        tile[i][tx] = W2[(long)(m0 + i) * HC + k0 + tx];
    __syncthreads();
    #pragma unroll
    for (int i = ty; i < 32; i += 8)
        g_W2T[(long)(k0 + i) * HC + m0 + tx] = tile[tx][i];
}

// ---------------- CSR build (decoupled 3-kernel scan) ----------------------
__global__ void k_csr_count(const int* __restrict__ dst) {
    int e = blockIdx.x * blockDim.x + threadIdx.x;
    if (e < N_EDGES) atomicAdd(&g_cnt[dst[e]], 1);
}
__global__ __launch_bounds__(256) void k_scanA() {
    __shared__ int s[256];
    int b = blockIdx.x, tid = threadIdx.x;
    int i = b * 256 + tid;
    int v = (i < N_NODES) ? g_cnt[i] : 0;
    s[tid] = v;
    __syncthreads();
    #pragma unroll
    for (int off = 1; off < 256; off <<= 1) {
        int t = (tid >= off) ? s[tid - off] : 0;
        __syncthreads();
        s[tid] += t;
        __syncthreads();
    }
    if (i <= N_NODES) g_off[i] = s[tid] - v;
    if (tid == 255) g_bsum[b] = s[255];
}
__global__ __launch_bounds__(128) void k_scanB() {
    __shared__ int s[128];
    int tid = threadIdx.x;
    int v = (tid < SCB) ? g_bsum[tid] : 0;
    s[tid] = v;
    __syncthreads();
    #pragma unroll
    for (int off = 1; off < 128; off <<= 1) {
        int t = (tid >= off) ? s[tid - off] : 0;
        __syncthreads();
        s[tid] += t;
        __syncthreads();
    }
    if (tid < SCB) g_boff[tid] = s[tid] - v;
}
__global__ void k_scanC() {
    int i = blockIdx.x * 256 + threadIdx.x;
    if (i < N_NODES) g_off[i] += g_boff[i >> 8];
    if (i == 0) g_off[N_NODES] = N_EDGES;
}
__global__ void k_csr_scatter(const int* __restrict__ src,
                              const int* __restrict__ dst,
                              const int* __restrict__ etype,
                              const int* __restrict__ batch) {
    int e = blockIdx.x * blockDim.x + threadIdx.x;
    if (e < N_EDGES) {
        int d = dst[e];
        int p = atomicAdd(&g_cur[d], 1);
        int pos = g_off[d] + p;
        g_srcp[pos] = src[e];
        g_dstp[pos] = d;
        g_etp[pos]  = etype[e];
        g_gbp[pos]  = batch[d];
    }
}

// ---------------- generic fold W·a (src/dst) -> out[k*8+j] -----------------
__global__ void k_fold_v(const float* __restrict__ W,
                         const float* __restrict__ a_s,
                         const float* __restrict__ a_d,
                         float* __restrict__ out, int K) {
    int wid = (blockIdx.x * blockDim.x + threadIdx.x) >> 5;
    int lane = threadIdx.x & 31;
    if (wid >= K * 8) return;
    int k = wid >> 3, j = wid & 7;
    const float* a = (j < 4) ? (a_s + j * HID) : (a_d + (j - 4) * HID);
    int cb = (j & 3) * HID;
    float s = 0.f;
    #pragma unroll
    for (int c = lane; c < HID; c += 32)
        s += W[(long)k * HC + cb + c] * a[c];
    #pragma unroll
    for (int o = 16; o; o >>= 1) s += __shfl_down_sync(0xffffffffu, s, o);
    if (lane == 0) out[k * 8 + j] = s;
}

__global__ void k_al1() {
    int n = blockIdx.x * 256 + threadIdx.x;
    if (n >= N_NODES) return;
    float p[8];
    #pragma unroll
    for (int j = 0; j < 8; j++) p[j] = 0.f;
    for (int k = 0; k < FEAT; k++) {
        float x = g_x[(long)n * KP1 + k];
        #pragma unroll
        for (int j = 0; j < 8; j++) p[j] += x * g_v1[k * 8 + j];
    }
    #pragma unroll
    for (int j = 0; j < 4; j++) {
        g_als[n * HEADS + j] = p[j];
        g_ald[n * HEADS + j] = p[j + 4];
    }
}

__global__ __launch_bounds__(256) void k_al2(const float* __restrict__ F2) {
    int n = blockIdx.x;
    __shared__ float row[HC];
    int tid = threadIdx.x;
    for (int i = tid; i < HC; i += 256) row[i] = F2[(long)n * HC + i];
    __syncthreads();
    int w = tid >> 5, lane = tid & 31;
    float s = 0.f;
    for (int k = lane; k < HC; k += 32) s += row[k] * g_v[k * 8 + w];
    #pragma unroll
    for (int o = 16; o; o >>= 1) s += __shfl_down_sync(0xffffffffu, s, o);
    if (lane == 0) {
        if (w < 4) g_als[n * HEADS + w] = s;
        else       g_ald[n * HEADS + (w - 4)] = s;
    }
}

// ---------------- edge-type terms ------------------------------------------
__global__ void k_fold_u2(const float* __restrict__ We1,
                          const float* __restrict__ a_edge1,
                          const float* __restrict__ We2,
                          const float* __restrict__ a_edge2) {
    int wid = (blockIdx.x * blockDim.x + threadIdx.x) >> 5;
    int lane = threadIdx.x & 31;
    if (wid >= 2 * HC * HEADS) return;
    int layer = wid >= HC * HEADS;
    int w = wid - layer * HC * HEADS;
    int k = w >> 2, hh = w & 3;
    const float* We = layer ? We2 : We1;
    const float* ae = layer ? a_edge2 : a_edge1;
    float s = 0.f;
    #pragma unroll
    for (int c = lane; c < HID; c += 32)
        s += We[(long)k * HC + hh * HID + c] * ae[hh * HID + c];
    #pragma unroll
    for (int o = 16; o; o >>= 1) s += __shfl_down_sync(0xffffffffu, s, o);
    if (lane == 0) g_u[layer * HC * HEADS + k * HEADS + hh] = s;
}

__global__ void k_alet2(const float* __restrict__ edge_emb) {
    int wid = (blockIdx.x * blockDim.x + threadIdx.x) >> 5;
    int lane = threadIdx.x & 31;
    if (wid >= 2 * N_ETYPES * HEADS) return;
    int layer = wid >= N_ETYPES * HEADS;
    int w = wid - layer * N_ETYPES * HEADS;
    int t = w >> 2, hh = w & 3;
    const float* u = g_u + layer * HC * HEADS;
    float s = 0.f;
    for (int k = lane; k < HC; k += 32)
        s += edge_emb[(long)t * HC + k] * u[k * HEADS + hh];
    #pragma unroll
    for (int o = 16; o; o >>= 1) s += __shfl_down_sync(0xffffffffu, s, o);
    if (lane == 0) g_alet[layer * N_ETYPES * HEADS + t * HEADS + hh] = s;
}

// ---------------- edge-parallel exp(leaky(logit)) --------------------------
__global__ void k_eexp(int layer) {
    int j = blockIdx.x * 256 + threadIdx.x;
    if (j >= N_EDGES) return;
    const float* alet = g_alet + layer * N_ETYPES * HEADS;
    float4 as = *(const float4*)&g_als[g_srcp[j] * HEADS];
    float4 ad = *(const float4*)&g_ald[g_dstp[j] * HEADS];
    float4 at = *(const float4*)&alet[g_etp[j] * HEADS];
    float l0 = as.x + ad.x + at.x;
    float l1 = as.y + ad.y + at.y;
    float l2 = as.z + ad.z + at.z;
    float l3 = as.w + ad.w + at.w;
    l0 = (l0 >= 0.f) ? l0 : 0.2f * l0;
    l1 = (l1 >= 0.f) ? l1 : 0.2f * l1;
    l2 = (l2 >= 0.f) ? l2 : 0.2f * l2;
    l3 = (l3 >= 0.f) ? l3 : 0.2f * l3;
    float4 v = make_float4(expf(l0), expf(l1), expf(l2), expf(l3));
    *(float4*)&g_alpha[j * HEADS] = v;
}

// ---------------- per-node denominator + normalize -------------------------
__global__ void k_den() {
    int n = blockIdx.x * 256 + threadIdx.x;
    if (n >= N_NODES) return;
    int a = g_off[n], b = g_off[n + 1];
    float4 den = make_float4(0.f, 0.f, 0.f, 0.f);
    for (int j = a; j < b; j++) {
        float4 v = *(const float4*)&g_alpha[j * HEADS];
        den.x += v.x; den.y += v.y; den.z += v.z; den.w += v.w;
    }
    float4 inv = make_float4(1.f / (den.x + 1e-16f), 1.f / (den.y + 1e-16f),
                             1.f / (den.z + 1e-16f), 1.f / (den.w + 1e-16f));
    for (int j = a; j < b; j++) {
        float4 v = *(const float4*)&g_alpha[j * HEADS];
        v.x *= inv.x; v.y *= inv.y; v.z *= inv.z; v.w *= inv.w;
        *(float4*)&g_alpha[j * HEADS] = v;
    }
}

// ---------------- layer-1 aggregation in FEAT space ------------------------
__global__ __launch_bounds__(128) void k_aggX() {
    int n = blockIdx.x;
    int tid = threadIdx.x;
    float a0 = 0.f, a1 = 0.f, a2 = 0.f, a3 = 0.f;
    int a = g_off[n], b = g_off[n + 1];
    for (int j = a; j < b; j++) {
        float4 al = *(const float4*)&g_alpha[j * 4];
        float x = (tid < KP1) ? g_x[(long)g_srcp[j] * KP1 + tid] : 0.f;
        a0 += al.x * x;
        a1 += al.y * x;
        a2 += al.z * x;
        a3 += al.w * x;
    }
    if (tid < KP1) {
        float* op = g_aggX + (long)n * AXW + tid;
        op[0 * KP1] = a0;
        op[1 * KP1] = a1;
        op[2 * KP1] = a2;
        op[3 * KP1] = a3;
    }
}

// ---------------- layer-2: edge-parallel weighted F2 sums ------------------
__global__ __launch_bounds__(256) void k_eagg2(const float* __restrict__ F2) {
    __shared__ int    s_src[256];
    __shared__ int    s_g[256];
    __shared__ float4 s_al[256];
    int tid = threadIdx.x;
    int j0 = blockIdx.x * 256;
    s_src[tid] = g_srcp[j0 + tid];
    s_g[tid]   = g_gbp[j0 + tid];
    s_al[tid]  = *(const float4*)&g_alpha[(j0 + tid) * 4];
    __syncthreads();

    const int c = tid * 4;
    float a0[4] = {0.f, 0.f, 0.f, 0.f};
    float a1[4] = {0.f, 0.f, 0.f, 0.f};
    float a2[4] = {0.f, 0.f, 0.f, 0.f};
    float a3[4] = {0.f, 0.f, 0.f, 0.f};
    int curg = s_g[0];

    auto flush = [&](int g) {
        #pragma unroll
        for (int q = 0; q < 4; q++) {
            if (a0[q] != 0.f) atomicAdd(&g_E[(g * HEADS + 0) * HC + c + q], a0[q]);
            if (a1[q] != 0.f) atomicAdd(&g_E[(g * HEADS + 1) * HC + c + q], a1[q]);
            if (a2[q] != 0.f) atomicAdd(&g_E[(g * HEADS + 2) * HC + c + q], a2[q]);
            if (a3[q] != 0.f) atomicAdd(&g_E[(g * HEADS + 3) * HC + c + q], a3[q]);
            a0[q] = a1[q] = a2[q] = a3[q] = 0.f;
        }
    };

    for (int i = 0; i < 256; i++) {
        int g = s_g[i];
        if (g != curg) { flush(curg); curg = g; }
        float4 f = *(const float4*)(F2 + (long)s_src[i] * HC + c);
        float4 al = s_al[i];
        a0[0] += al.x * f.x; a0[1] += al.x * f.y; a0[2] += al.x * f.z; a0[3] += al.x * f.w;
        a1[0] += al.y * f.x; a1[1] += al.y * f.y; a1[2] += al.y * f.z; a1[3] += al.y * f.w;
        a2[0] += al.z * f.x; a2[1] += al.z * f.y; a2[2] += al.z * f.z; a2[3] += al.z * f.w;
        a3[0] += al.w * f.x; a3[1] += al.w * f.y; a3[2] += al.w * f.z; a3[3] += al.w * f.w;
    }
    flush(curg);
}

// ---------------- per-graph counts / cvec ----------------------------------
__global__ void k_gcnt(const int* __restrict__ batch) {
    int i = blockIdx.x * blockDim.x + threadIdx.x;
    if (i < N_NODES) atomicAdd(&g_gcnt[batch[i]], 1.f);
}

__global__ void k_cvec(const float* __restrict__ b2,
                       const float* __restrict__ projW,
                       const float* __restrict__ projb) {
    int d = threadIdx.x;
    float s = projb[d];
    for (int k = 0; k < HC; k++) s += b2[k] * projW[(long)k * HID + d];
    g_cvec[d] = s;
}

// ---------------- smem-staged head partials --------------------------------
// grid (HEADS, 32 k-chunks); stages Q chunk + E chunk; atomics into g_part
__global__ __launch_bounds__(256) void k_partQ2() {
    __shared__ float Qs[32][256];
    __shared__ float Es[64][32];
    int h = blockIdx.x, kc = blockIdx.y;
    int tid = threadIdx.x;
    int k0 = kc * 32;
    const float* qp = g_Q + (long)h * HC * HID;
    #pragma unroll
    for (int i = 0; i < 32; i++)
        Qs[i][tid] = qp[(long)(k0 + i) * HID + tid];
    for (int i = tid; i < 64 * 32; i += 256) {
        int g = i >> 5, k = i & 31;
        Es[g][k] = g_E[(g * HEADS + h) * HC + k0 + k];
    }
    __syncthreads();
    for (int g = 0; g < 64; g++) {
        float acc = 0.f;
        #pragma unroll
        for (int k = 0; k < 32; k++) acc += Es[g][k] * Qs[k][tid];
        atomicAdd(&g_part[(long)(g * HEADS + h) * HID + tid], acc);
    }
}

__global__ __launch_bounds__(256) void k_final3(const float* __restrict__ lng,
                                                const float* __restrict__ lnb,
                                                float* __restrict__ out) {
    int g = blockIdx.x;
    int d = threadIdx.x;
    __shared__ float red[256];
    float inv = 1.f / fmaxf(g_gcnt[g], 1.f);
    const float* pp = g_part + (long)g * HEADS * HID + d;
    float acc = pp[0] + pp[HID] + pp[2 * HID] + pp[3 * HID];
    float y = acc * inv + g_cvec[d];
    red[d] = y;
    __syncthreads();
    #pragma unroll
    for (int off = 128; off; off >>= 1) {
        if (d < off) red[d] += red[d + off];
        __syncthreads();
    }
    float mu = red[0] / (float)HID;
    __syncthreads();
    float dv = y - mu;
    red[d] = dv * dv;
    __syncthreads();
    #pragma unroll
    for (int off = 128; off; off >>= 1) {
        if (d < off) red[d] += red[d + off];
        __syncthreads();
    }
    float var = red[0] / (float)HID;
    float r = dv * rsqrtf(var + 1e-5f) * lng[d] + lnb[d];
    out[g * HID + d] = fmaxf(r, 0.f);
}

// ---------------- host orchestration ---------------------------------------
static float* sym(const void* s) {
    void* p = 0;
    cudaGetSymbolAddress(&p, s);
    return (float*)p;
}

extern "C" void kernel_launch(void* const* d_in, const int* in_sizes, int n_in,
                              void* d_out, int out_size) {
    const int*   x_idx    = (const int*)d_in[0];
    const int*   eidx     = (const int*)d_in[1];
    const int*   etype    = (const int*)d_in[2];
    const int*   batch    = (const int*)d_in[3];
    const float* node_emb = (const float*)d_in[4];
    const float* edge_emb = (const float*)d_in[5];
    const float* W1     = (const float*)d_in[6];
    const float* a_src1 = (const float*)d_in[7];
    const float* a_dst1 = (const float*)d_in[8];
    const float* a_edge1= (const float*)d_in[9];
    const float* We1    = (const float*)d_in[10];
    const float* b1     = (const float*)d_in[11];
    const float* W2     = (const float*)d_in[12];
    const float* a_src2 = (const float*)d_in[13];
    const float* a_dst2 = (const float*)d_in[14];
    const float* a_edge2= (const float*)d_in[15];
    const float* We2    = (const float*)d_in[16];
    const float* b2     = (const float*)d_in[17];
    const float* projW  = (const float*)d_in[18];
    const float* projb  = (const float*)d_in[19];
    const float* lng    = (const float*)d_in[20];
    const float* lnb    = (const float*)d_in[21];
    float* out = (float*)d_out;

    const int* src = eidx;
    const int* dst = eidx + N_EDGES;

    float* p_aggX = sym(g_aggX);
    float* p_W1p  = sym(g_W1p);
    float* p_W2T  = sym(g_W2T);
    float* p_feat = sym(g_feat);
    float* p_v    = sym(g_v);
    float* p_v1   = sym(g_v1);

    static cudaStream_t s2 = 0;
    static cudaEvent_t evF = 0, evJ1 = 0, evJ = 0;
    if (!s2) {
        cudaStreamCreateWithFlags(&s2, cudaStreamNonBlocking);
        cudaEventCreateWithFlags(&evF, cudaEventDisableTiming);
        cudaEventCreateWithFlags(&evJ1, cudaEventDisableTiming);
        cudaEventCreateWithFlags(&evJ, cudaEventDisableTiming);
    }

    dim3 fgrid(2, MP / 128, HEADS);
    dim3 w2tgrid(HC / 32, HC / 32);
    dim3 qgrid(HID / 128, HC / 128, HEADS);
    dim3 p2grid(HEADS, 32);

    // ---- main stream: critical path ----
    k_prep1<<<(N_GRAPHS * HEADS * HC + 255) / 256, 256>>>(W1);

    // fork side stream: early group (needed by al1/eexp), then late group
    cudaEventRecord(evF, 0);
    cudaStreamWaitEvent(s2, evF, 0);
    k_fold_v<<<(FEAT * 8 * 32 + 255) / 256, 256, 0, s2>>>(W1, a_src1, a_dst1, p_v1, FEAT);
    k_fold_u2<<<(2 * HC * HEADS * 32 + 255) / 256, 256, 0, s2>>>(We1, a_edge1, We2, a_edge2);
    k_alet2<<<(2 * N_ETYPES * HEADS * 32 + 255) / 256, 256, 0, s2>>>(edge_emb);
    cudaEventRecord(evJ1, s2);
    k_w2t<<<w2tgrid, dim3(32, 8), 0, s2>>>(W2);
    k_qfold<<<qgrid, 256, 0, s2>>>(p_W2T, projW);
    k_fold_v<<<(HC * 8 * 32 + 255) / 256, 256, 0, s2>>>(W2, a_src2, a_dst2, p_v, HC);
    k_cvec<<<1, HID, 0, s2>>>(b2, projW, projb);
    k_gcnt<<<(N_NODES + 255) / 256, 256, 0, s2>>>(batch);
    cudaEventRecord(evJ, s2);

    k_gatherX<<<(N_NODES * KP1 + 255) / 256, 256>>>(x_idx, node_emb);
    k_csr_count<<<(N_EDGES + 255) / 256, 256>>>(dst);
    k_scanA<<<SCB, 256>>>();
    k_scanB<<<1, 128>>>();
    k_scanC<<<(N_NODES + 255) / 256, 256>>>();
    k_csr_scatter<<<(N_EDGES + 255) / 256, 256>>>(src, dst, etype, batch);

    // join early side work, then layer 1
    cudaStreamWaitEvent(0, evJ1, 0);
    k_al1<<<(N_NODES + 255) / 256, 256>>>();
    k_eexp<<<(N_EDGES + 255) / 256, 256>>>(0);
    k_den<<<(N_NODES + 255) / 256, 256>>>();
    k_aggX<<<N_NODES, 128>>>();
    k_gemmF<<<fgrid, 256>>>(p_aggX, p_W1p, b1, p_feat);

    // join late side work (al2 needs g_v; head needs Q/cvec/gcnt)
    cudaStreamWaitEvent(0, evJ, 0);
    k_al2<<<N_NODES, 256>>>(p_feat);

    // layer 2
    k_eexp<<<(N_EDGES + 255) / 256, 256>>>(1);
    k_den<<<(N_NODES + 255) / 256, 256>>>();
    k_eagg2<<<N_EDGES / 256, 256>>>(p_feat);

    // head
    k_partQ2<<<p2grid, 256>>>();
    k_final3<<<N_GRAPHS, 256>>>(lng, lnb, out);
}